// round 11
// baseline (speedup 1.0000x reference)
#include <cuda_runtime.h>
#include <cuda_fp16.h>
#include <cstdint>
#include <cstddef>

// ---------------------------------------------------------------------------
// FeaturePropogate via mma.sync fp16 (plain sm_103 PTX):
//   - interp pushed through first MLP layer (W*concat == W_a*feat + interp(W_b*F))
//   - GEMMs: fp16 mma.sync, fp32 accum (validated error ~1.9e-4)
//   - block tile 128(o) x 256(n), warp tile 32x64, K-chunk 32
//   - 4-stage cp.async pipeline (prefetch depth 3), one __syncthreads per chunk
// ---------------------------------------------------------------------------

#define B_     4
#define N0_    8192
#define N1_    2048
#define N2_    512

// ---- device scratch (no allocation allowed) ----
__device__ __half g_l1h[(size_t)B_*N1_*128];
__device__ __half g_l2h[(size_t)B_*N2_*192];
__device__ __half g_rdh[(size_t)B_*N0_*64];
__device__ __half g_w21ah[640*320];
__device__ __half g_w21bh[640*640];
__device__ __half g_w10ah[640*704];
__device__ __half g_w10bh[768*640];
__device__ __half g_Y1h[(size_t)B_*N1_*640];
__device__ __half g_Fh [(size_t)B_*N1_*640];
__device__ __half g_Y3h[(size_t)B_*N0_*640];
__device__ float g_G2[(size_t)B_*N2_*640];
__device__ float g_H1[(size_t)B_*N1_*640];
__device__ float g_G [(size_t)B_*N1_*640];
__device__ float g_Hr[(size_t)B_*N0_*640];
__device__ int   g_i1[(size_t)B_*N1_*8];
__device__ float g_w1[(size_t)B_*N1_*8];
__device__ int   g_i0[(size_t)B_*N0_*8];
__device__ float g_w0[(size_t)B_*N0_*8];

__device__ __forceinline__ uint32_t smem_u32_of(const void* p) {
    uint32_t a;
    asm("{ .reg .u64 t; cvta.to.shared.u64 t, %1; cvt.u32.u64 %0, t; }" : "=r"(a) : "l"(p));
    return a;
}
__device__ __forceinline__ void ldsm4(uint32_t* r, uint32_t addr) {
    asm volatile("ldmatrix.sync.aligned.m8n8.x4.shared.b16 {%0,%1,%2,%3}, [%4];"
                 : "=r"(r[0]), "=r"(r[1]), "=r"(r[2]), "=r"(r[3]) : "r"(addr));
}
__device__ __forceinline__ void mma16816(float* d, const uint32_t* a, const uint32_t* b) {
    asm volatile(
        "mma.sync.aligned.m16n8k16.row.col.f32.f16.f16.f32 "
        "{%0,%1,%2,%3}, {%4,%5,%6,%7}, {%8,%9}, {%0,%1,%2,%3};"
        : "+f"(d[0]), "+f"(d[1]), "+f"(d[2]), "+f"(d[3])
        : "r"(a[0]), "r"(a[1]), "r"(a[2]), "r"(a[3]), "r"(b[0]), "r"(b[1]));
}
__device__ __forceinline__ void cp16(uint32_t saddr, const void* gaddr) {
    asm volatile("cp.async.cg.shared.global [%0], [%1], 16;" :: "r"(saddr), "l"(gaddr));
}

// ---------------------------------------------------------------------------
// KNN top-8 (verified R3). D: [B][M][Npts], point n reads column n.
// ---------------------------------------------------------------------------
__global__ __launch_bounds__(256)
void knn_topk(const float* __restrict__ D, int M, int Npts,
              int* __restrict__ out_i, float* __restrict__ out_w)
{
    __shared__ float sd[64][4][8];
    __shared__ int   si[64][4][8];
    const int b   = blockIdx.y;
    const int p   = threadIdx.x & 63;
    const int q   = threadIdx.x >> 6;
    const int n   = blockIdx.x * 64 + p;
    const int seg = M >> 2;

    float bd[8]; int bi[8];
    #pragma unroll
    for (int j = 0; j < 8; ++j) { bd[j] = 3.4e38f; bi[j] = 0; }
    const float* col = D + (size_t)b * M * Npts + n + (size_t)(q * seg) * Npts;
    #pragma unroll 8
    for (int m = 0; m < seg; ++m) {
        float v = __ldg(col + (size_t)m * Npts);
        if (v < bd[7]) {
            bd[7] = v; bi[7] = q * seg + m;
            #pragma unroll
            for (int r = 7; r >= 1; --r) {
                if (bd[r] < bd[r-1]) {
                    float td = bd[r]; bd[r] = bd[r-1]; bd[r-1] = td;
                    int   ti = bi[r]; bi[r] = bi[r-1]; bi[r-1] = ti;
                }
            }
        }
    }
    #pragma unroll
    for (int j = 0; j < 8; ++j) { sd[p][q][j] = bd[j]; si[p][q][j] = bi[j]; }
    __syncthreads();

    if (threadIdx.x < 64) {
        const int pp = threadIdx.x;
        int p0 = 0, p1 = 0, p2 = 0, p3 = 0;
        float d8[8]; int i8[8];
        #pragma unroll
        for (int k = 0; k < 8; ++k) {
            float v0 = sd[pp][0][p0], v1 = sd[pp][1][p1];
            float v2 = sd[pp][2][p2], v3 = sd[pp][3][p3];
            float m01 = v0; int q01 = 0; if (v1 < m01) { m01 = v1; q01 = 1; }
            float m23 = v2; int q23 = 2; if (v3 < m23) { m23 = v3; q23 = 3; }
            float mv = m01; int qq = q01; if (m23 < m01) { mv = m23; qq = q23; }
            d8[k] = mv;
            if      (qq == 0) i8[k] = si[pp][0][p0++];
            else if (qq == 1) i8[k] = si[pp][1][p1++];
            else if (qq == 2) i8[k] = si[pp][2][p2++];
            else              i8[k] = si[pp][3][p3++];
        }
        float w[8], s = 0.f;
        #pragma unroll
        for (int j = 0; j < 8; ++j) { w[j] = 1.f / (d8[j] + 1e-8f); s += w[j]; }
        float inv = 1.f / (s + 1e-8f);
        const int nn = blockIdx.x * 64 + pp;
        size_t base = ((size_t)b * Npts + nn) * 8;
        #pragma unroll
        for (int j = 0; j < 8; ++j) { out_i[base + j] = i8[j]; out_w[base + j] = w[j] * inv; }
    }
}

// ---------------------------------------------------------------------------
// convert fp32 -> fp16
// ---------------------------------------------------------------------------
__global__ __launch_bounds__(256)
void cvt_x_half(const float* __restrict__ x, __half* __restrict__ hi, int n4)
{
    int i = blockIdx.x * 256 + threadIdx.x;
    if (i >= n4) return;
    float4 v = ((const float4*)x)[i];
    ((__half2*)hi)[i*2+0] = __halves2half2(__float2half_rn(v.x), __float2half_rn(v.y));
    ((__half2*)hi)[i*2+1] = __halves2half2(__float2half_rn(v.z), __float2half_rn(v.w));
}

// ---------------------------------------------------------------------------
// combine: v = ReLU(sc*(H[n] + sum_j w_j G[idx_j]) + bb) -> single fp16 plane
// ---------------------------------------------------------------------------
__global__ __launch_bounds__(256)
void combine_bn_relu(const float* __restrict__ H,    // [B][Np][640]
                     const float* __restrict__ G,    // [B][Ng][640]
                     const int*   __restrict__ knn_i,
                     const float* __restrict__ knn_w,
                     const float* __restrict__ bias,
                     const float* __restrict__ gamma,
                     const float* __restrict__ beta,
                     __half* __restrict__ Yh, int Np, int Ng)
{
    __shared__ float s_sc[640], s_bb[640];
    const float BNS = 0.99999500003749968f;   // 1/sqrt(1+1e-5)
    for (int c = threadIdx.x; c < 640; c += 256) {
        float sc = __ldg(gamma + c) * BNS;
        s_sc[c] = sc;
        s_bb[c] = sc * __ldg(bias + c) + __ldg(beta + c);
    }
    __syncthreads();
    const int b    = blockIdx.y;
    const int warp = threadIdx.x >> 5, lane = threadIdx.x & 31;
    const int n    = blockIdx.x * 8 + warp;
    const size_t pbase = (size_t)b * Np + n;

    int idx[8]; float w8[8];
    const int*   ip = knn_i + pbase * 8;
    const float* wp = knn_w + pbase * 8;
    #pragma unroll
    for (int j = 0; j < 8; ++j) { idx[j] = __ldg(ip + j); w8[j] = __ldg(wp + j); }

    const float* h = H + pbase * 640;
    float acc[20];
    #pragma unroll
    for (int r = 0; r < 20; ++r) acc[r] = __ldg(h + lane + 32 * r);
    #pragma unroll
    for (int j = 0; j < 8; ++j) {
        const float* g = G + ((size_t)b * Ng + idx[j]) * 640;
        const float wj = w8[j];
        #pragma unroll
        for (int r = 0; r < 20; ++r) acc[r] += wj * __ldg(g + lane + 32 * r);
    }
    #pragma unroll
    for (int r = 0; r < 20; ++r) {
        int c = lane + 32 * r;
        float v = fmaxf(s_sc[c] * acc[r] + s_bb[c], 0.f);
        Yh[pbase * 640 + c] = __float2half_rn(v);
    }
}

// ---------------------------------------------------------------------------
// mma.sync fp16 GEMM:  D[o][n] = sum_k W[o][k] * X[n][k]
// Block tile 128(o) x 256(n), warp tile 32x64 (4x4 warps, 512 threads).
// K-chunk 32, 4-stage cp.async pipeline, one __syncthreads per chunk.
// Smem row stride 80 B: LDSM conflict-free (banks 0,20,8,28,16,4,24,12).
// Epilogue: two 128x128 passes through smem.
// mode: 0 = channel-major fp32 + BN+ReLU
//       1 = point-major fp16 + BN+ReLU
//       2 = point-major fp32 raw
// ---------------------------------------------------------------------------
#define PLANE_A     10240              // 128 rows x 80 B
#define PLANE_B     20480              // 256 rows x 80 B
#define STAGE_BYTES (PLANE_A + PLANE_B)
#define GEMM_SMEM   (4 * STAGE_BYTES)  // 122880; epilogue (67584 B) reuses it

__global__ __launch_bounds__(512)
void gemm_mma(const __half* __restrict__ Wh, int ldW,
              const __half* __restrict__ Xh,
              float* __restrict__ Yf, __half* __restrict__ Yhp,
              const float* __restrict__ bias, const float* __restrict__ gamma,
              const float* __restrict__ beta,
              int K, int N, int O, int mode)
{
    extern __shared__ char dsm[];
    const uint32_t sbase = smem_u32_of(dsm);
    const int t = threadIdx.x, lane = t & 31, w = t >> 5;
    const int wm = w >> 2, wn = w & 3;     // warp tile: o = wm*32, n = wn*64
    const int b  = blockIdx.z;
    const int n0 = blockIdx.x * 256;
    const int o0 = blockIdx.y * 128;

    const __half* srcA = Wh + (size_t)o0 * ldW;
    const __half* srcB = Xh + ((size_t)b * N + n0) * K;

    float acc[2][8][4];
    #pragma unroll
    for (int i = 0; i < 2; ++i)
        #pragma unroll
        for (int j = 0; j < 8; ++j)
            #pragma unroll
            for (int e = 0; e < 4; ++e) acc[i][j][e] = 0.f;

    // stage loader: A 128x32 halves + B 256x32 halves, padded stride 80 B.
    // A: 512 cp16 (one/thread). B: 1024 cp16 (two/thread).
    auto cp_stage = [&](int k0, int buf) {
        uint32_t sb = sbase + buf * STAGE_BYTES;
        {
            int row = t >> 2, c4 = t & 3;
            cp16(sb + row * 80 + c4 * 16, srcA + (size_t)row * ldW + k0 + c4 * 8);
        }
        #pragma unroll
        for (int u = 0; u < 2; ++u) {
            int idx = t * 2 + u;
            int row = idx >> 2, c4 = idx & 3;
            cp16(sb + PLANE_A + row * 80 + c4 * 16,
                 srcB + (size_t)row * K + k0 + c4 * 8);
        }
        asm volatile("cp.async.commit_group;" ::: "memory");
    };

    const int g = lane >> 3;
    const int arow_off = (g & 1) * 8 + (lane & 7);
    const int acol_off = (g >> 1) * 8;
    const int brow_off = (g >> 1) * 8 + (lane & 7);
    const int bcol_off = (g & 1) * 8;

    const int nc = K >> 5;
    cp_stage(0, 0);
    if (nc > 1) cp_stage(32, 1);
    if (nc > 2) cp_stage(64, 2);

    int buf = 0;
    for (int it = 0; it < nc; ++it) {
        const int rem = nc - 1 - it;
        if (rem >= 2)      asm volatile("cp.async.wait_group 2;" ::: "memory");
        else if (rem == 1) asm volatile("cp.async.wait_group 1;" ::: "memory");
        else               asm volatile("cp.async.wait_group 0;" ::: "memory");
        __syncthreads();
        if (it + 3 < nc) {
            int nb = buf + 3; if (nb >= 4) nb -= 4;
            cp_stage((it + 3) << 5, nb);
        }

        const uint32_t pA = sbase + buf * STAGE_BYTES;
        const uint32_t pB = pA + PLANE_A;
        #pragma unroll
        for (int ks = 0; ks < 2; ++ks) {
            uint32_t ah[2][4];
            #pragma unroll
            for (int mt = 0; mt < 2; ++mt) {
                uint32_t ad = (uint32_t)(wm * 32 + mt * 16 + arow_off) * 80
                            + (uint32_t)(ks * 16 + acol_off) * 2;
                ldsm4(ah[mt], pA + ad);
            }
            #pragma unroll
            for (int np = 0; np < 4; ++np) {
                uint32_t bd = (uint32_t)(wn * 64 + np * 16 + brow_off) * 80
                            + (uint32_t)(ks * 16 + bcol_off) * 2;
                uint32_t bh[4];
                ldsm4(bh, pB + bd);
                #pragma unroll
                for (int mt = 0; mt < 2; ++mt)
                    #pragma unroll
                    for (int nj = 0; nj < 2; ++nj)
                        mma16816(acc[mt][np * 2 + nj], ah[mt], bh + nj * 2);
            }
        }
        ++buf; if (buf == 4) buf = 0;
    }
    __syncthreads();   // all MMA reads done before smem reuse

    // ---- epilogue: two 128x128 passes through smem (stride 132 floats) ----
    float* smf = (float*)dsm;
    const float BNS = 0.99999500003749968f;
    #pragma unroll
    for (int h = 0; h < 2; ++h) {
        if ((wn >> 1) == h) {
            const int cb = (wn & 1) * 64 + (lane & 3) * 2;
            const int rb = wm * 32 + (lane >> 2);
            #pragma unroll
            for (int mt = 0; mt < 2; ++mt)
                #pragma unroll
                for (int np = 0; np < 4; ++np)
                    #pragma unroll
                    for (int nj = 0; nj < 2; ++nj) {
                        const float* a4 = acc[mt][np * 2 + nj];
                        int r = rb + mt * 16;
                        int c = cb + np * 16 + nj * 8;
                        if (mode == 0) {
                            smf[r * 132 + c]           = a4[0];
                            smf[r * 132 + c + 1]       = a4[1];
                            smf[(r + 8) * 132 + c]     = a4[2];
                            smf[(r + 8) * 132 + c + 1] = a4[3];
                        } else {
                            smf[c * 132 + r]           = a4[0];
                            smf[(c + 1) * 132 + r]     = a4[1];
                            smf[c * 132 + r + 8]       = a4[2];
                            smf[(c + 1) * 132 + r + 8] = a4[3];
                        }
                    }
        }
        __syncthreads();

        if (mode == 0) {
            int o = t >> 2, nch = (t & 3) * 32;
            float sc = __ldg(gamma + o0 + o) * BNS;
            float bb = sc * __ldg(bias + o0 + o) + __ldg(beta + o0 + o);
            float* dst = Yf + ((size_t)b * O + o0 + o) * N + n0 + h * 128 + nch;
            #pragma unroll
            for (int j = 0; j < 32; j += 4) {
                float4 v;
                v.x = fmaxf(sc * smf[o * 132 + nch + j]     + bb, 0.f);
                v.y = fmaxf(sc * smf[o * 132 + nch + j + 1] + bb, 0.f);
                v.z = fmaxf(sc * smf[o * 132 + nch + j + 2] + bb, 0.f);
                v.w = fmaxf(sc * smf[o * 132 + nch + j + 3] + bb, 0.f);
                *(float4*)(dst + j) = v;
            }
        } else if (mode == 2) {
            int nl = t >> 2, och = (t & 3) * 32;
            float* dst = Yf + ((size_t)b * N + n0 + h * 128 + nl) * O + o0 + och;
            #pragma unroll
            for (int j = 0; j < 32; j += 4) {
                float4 v;
                v.x = smf[nl * 132 + och + j];
                v.y = smf[nl * 132 + och + j + 1];
                v.z = smf[nl * 132 + och + j + 2];
                v.w = smf[nl * 132 + och + j + 3];
                *(float4*)(dst + j) = v;
            }
        } else {
            int nl = t >> 2, och = (t & 3) * 32;
            size_t off = ((size_t)b * N + n0 + h * 128 + nl) * O + o0 + och;
            #pragma unroll
            for (int j0 = 0; j0 < 32; j0 += 8) {
                union { __half hh[8]; uint4 u; } Hv;
                #pragma unroll
                for (int j = 0; j < 8; ++j) {
                    int o = o0 + och + j0 + j;
                    float sc = __ldg(gamma + o) * BNS;
                    float bb = sc * __ldg(bias + o) + __ldg(beta + o);
                    float v = fmaxf(sc * smf[nl * 132 + och + j0 + j] + bb, 0.f);
                    Hv.hh[j] = __float2half_rn(v);
                }
                *(uint4*)(Yhp + off + j0) = Hv.u;
            }
        }
        __syncthreads();
    }
}

// ---------------------------------------------------------------------------
extern "C" void kernel_launch(void* const* d_in, const int* in_sizes, int n_in,
                              void* d_out, int out_size)
{
    const float* radar = (const float*)d_in[0];
    const float* l1f   = (const float*)d_in[1];
    const float* l2f   = (const float*)d_in[2];
    const float* l0_l1 = (const float*)d_in[3];
    const float* l1_l2 = (const float*)d_in[4];
    const float* w21a  = (const float*)d_in[5];
    const float* b21a  = (const float*)d_in[6];
    const float* g21a  = (const float*)d_in[7];
    const float* be21a = (const float*)d_in[8];
    const float* w21b  = (const float*)d_in[9];
    const float* b21b  = (const float*)d_in[10];
    const float* g21b  = (const float*)d_in[11];
    const float* be21b = (const float*)d_in[12];
    const float* w10a  = (const float*)d_in[13];
    const float* b10a  = (const float*)d_in[14];
    const float* g10a  = (const float*)d_in[15];
    const float* be10a = (const float*)d_in[16];
    const float* w10b  = (const float*)d_in[17];
    const float* b10b  = (const float*)d_in[18];
    const float* g10b  = (const float*)d_in[19];
    const float* be10b = (const float*)d_in[20];

    cudaFuncSetAttribute(gemm_mma, cudaFuncAttributeMaxDynamicSharedMemorySize, GEMM_SMEM);

    __half *l1h,*l2h,*rdh;
    __half *w21ah,*w21bh,*w10ah,*w10bh;
    __half *Y1h,*Fh,*Y3h;
    float *G2,*H1,*G,*Hr,*w1,*w0;
    int *i1,*i0;
    cudaGetSymbolAddress((void**)&l1h, g_l1h);
    cudaGetSymbolAddress((void**)&l2h, g_l2h);
    cudaGetSymbolAddress((void**)&rdh, g_rdh);
    cudaGetSymbolAddress((void**)&w21ah, g_w21ah);
    cudaGetSymbolAddress((void**)&w21bh, g_w21bh);
    cudaGetSymbolAddress((void**)&w10ah, g_w10ah);
    cudaGetSymbolAddress((void**)&w10bh, g_w10bh);
    cudaGetSymbolAddress((void**)&Y1h, g_Y1h);
    cudaGetSymbolAddress((void**)&Fh,  g_Fh);
    cudaGetSymbolAddress((void**)&Y3h, g_Y3h);
    cudaGetSymbolAddress((void**)&G2, g_G2);     cudaGetSymbolAddress((void**)&H1, g_H1);
    cudaGetSymbolAddress((void**)&G,  g_G);      cudaGetSymbolAddress((void**)&Hr, g_Hr);
    cudaGetSymbolAddress((void**)&i1, g_i1);     cudaGetSymbolAddress((void**)&w1, g_w1);
    cudaGetSymbolAddress((void**)&i0, g_i0);     cudaGetSymbolAddress((void**)&w0, g_w0);

    // order chosen so ncu (-s 5 -c 1) lands on a GEMM whether or not the
    // harness's poison launch counts: positions 5 AND 6 are gemm_mma.
    cvt_x_half<<<(640*320/4 + 255)/256, 256>>>(w21a, w21ah, 640*320/4);            // 1
    cvt_x_half<<<(B_*N1_*128/4 + 255)/256, 256>>>(l1f, l1h, B_*N1_*128/4);         // 2
    cvt_x_half<<<(B_*N2_*192/4 + 255)/256, 256>>>(l2f, l2h, B_*N2_*192/4);         // 3
    knn_topk<<<dim3(N1_/64, B_), 256>>>(l1_l2, N2_, N1_, i1, w1);                  // 4
    gemm_mma<<<dim3(N1_/256, 5, B_), 512, GEMM_SMEM>>>(w21ah, 320, l1h,            // 5
        H1, nullptr, nullptr, nullptr, nullptr, 128, N1_, 640, 2);
    gemm_mma<<<dim3(N2_/256, 5, B_), 512, GEMM_SMEM>>>(w21ah+128, 320, l2h,        // 6
        G2, nullptr, nullptr, nullptr, nullptr, 192, N2_, 640, 2);
    knn_topk<<<dim3(N0_/64, B_), 256>>>(l0_l1, N1_, N0_, i0, w0);                  // 7
    combine_bn_relu<<<dim3(N1_/8, B_), 256>>>(H1, G2, i1, w1, b21a, g21a, be21a, Y1h, N1_, N2_);

    cvt_x_half<<<(640*640/4 + 255)/256, 256>>>(w21b, w21bh, 640*640/4);
    gemm_mma<<<dim3(N1_/256, 5, B_), 512, GEMM_SMEM>>>(w21bh, 640, Y1h,
        nullptr, Fh, b21b, g21b, be21b, 640, N1_, 640, 1);

    cvt_x_half<<<(640*704/4 + 255)/256, 256>>>(w10a, w10ah, 640*704/4);
    cvt_x_half<<<(B_*N0_*64/4 + 255)/256, 256>>>(radar, rdh, B_*N0_*64/4);
    gemm_mma<<<dim3(N1_/256, 5, B_), 512, GEMM_SMEM>>>(w10ah+64, 704, Fh,
        G, nullptr, nullptr, nullptr, nullptr, 640, N1_, 640, 2);
    gemm_mma<<<dim3(N0_/256, 5, B_), 512, GEMM_SMEM>>>(w10ah, 704, rdh,
        Hr, nullptr, nullptr, nullptr, nullptr, 64, N0_, 640, 2);
    combine_bn_relu<<<dim3(N0_/8, B_), 256>>>(Hr, G, i0, w0, b10a, g10a, be10a, Y3h, N0_, N1_);

    cvt_x_half<<<(768*640/4 + 255)/256, 256>>>(w10b, w10bh, 768*640/4);
    gemm_mma<<<dim3(N0_/256, 6, B_), 512, GEMM_SMEM>>>(w10bh, 640, Y3h,
        (float*)d_out, nullptr, b10b, g10b, be10b, 640, N0_, 768, 0);
}

// round 12
// speedup vs baseline: 1.3546x; 1.3546x over previous
#include <cuda_runtime.h>
#include <cuda_fp16.h>
#include <cstdint>
#include <cstddef>

// ---------------------------------------------------------------------------
// FeaturePropogate via mma.sync fp16 (plain sm_103 PTX):
//   - interp pushed through first MLP layer (W*concat == W_a*feat + interp(W_b*F))
//   - GEMMs: fp16 mma.sync, fp32 accum (R9 config: 128x128, K-chunk 64, 3-stage)
//   - KNN: 8 segments/point, 4-wide batched scan loads, 8-way sorted merge
// ---------------------------------------------------------------------------

#define B_     4
#define N0_    8192
#define N1_    2048
#define N2_    512

// ---- device scratch (no allocation allowed) ----
__device__ __half g_l1h[(size_t)B_*N1_*128];
__device__ __half g_l2h[(size_t)B_*N2_*192];
__device__ __half g_rdh[(size_t)B_*N0_*64];
__device__ __half g_w21ah[640*320];
__device__ __half g_w21bh[640*640];
__device__ __half g_w10ah[640*704];
__device__ __half g_w10bh[768*640];
__device__ __half g_Y1h[(size_t)B_*N1_*640];
__device__ __half g_Fh [(size_t)B_*N1_*640];
__device__ __half g_Y3h[(size_t)B_*N0_*640];
__device__ float g_G2[(size_t)B_*N2_*640];
__device__ float g_H1[(size_t)B_*N1_*640];
__device__ float g_G [(size_t)B_*N1_*640];
__device__ float g_Hr[(size_t)B_*N0_*640];
__device__ int   g_i1[(size_t)B_*N1_*8];
__device__ float g_w1[(size_t)B_*N1_*8];
__device__ int   g_i0[(size_t)B_*N0_*8];
__device__ float g_w0[(size_t)B_*N0_*8];

__device__ __forceinline__ uint32_t smem_u32_of(const void* p) {
    uint32_t a;
    asm("{ .reg .u64 t; cvta.to.shared.u64 t, %1; cvt.u32.u64 %0, t; }" : "=r"(a) : "l"(p));
    return a;
}
__device__ __forceinline__ void ldsm4(uint32_t* r, uint32_t addr) {
    asm volatile("ldmatrix.sync.aligned.m8n8.x4.shared.b16 {%0,%1,%2,%3}, [%4];"
                 : "=r"(r[0]), "=r"(r[1]), "=r"(r[2]), "=r"(r[3]) : "r"(addr));
}
__device__ __forceinline__ void mma16816(float* d, const uint32_t* a, const uint32_t* b) {
    asm volatile(
        "mma.sync.aligned.m16n8k16.row.col.f32.f16.f16.f32 "
        "{%0,%1,%2,%3}, {%4,%5,%6,%7}, {%8,%9}, {%0,%1,%2,%3};"
        : "+f"(d[0]), "+f"(d[1]), "+f"(d[2]), "+f"(d[3])
        : "r"(a[0]), "r"(a[1]), "r"(a[2]), "r"(a[3]), "r"(b[0]), "r"(b[1]));
}
__device__ __forceinline__ void cp16(uint32_t saddr, const void* gaddr) {
    asm volatile("cp.async.cg.shared.global [%0], [%1], 16;" :: "r"(saddr), "l"(gaddr));
}

// ---------------------------------------------------------------------------
// KNN top-8: 256 threads = 32 points x 8 segments. 4-wide batched scan,
// per-thread sorted top-8, then 8-way merge by one thread per point.
// D: [B][M][Npts], point n reads column n (coalesced across n).
// ---------------------------------------------------------------------------
__global__ __launch_bounds__(256)
void knn_topk(const float* __restrict__ D, int M, int Npts,
              int* __restrict__ out_i, float* __restrict__ out_w)
{
    __shared__ float sd[32][8][8];
    __shared__ int   si[32][8][8];
    const int b   = blockIdx.y;
    const int p   = threadIdx.x & 31;
    const int q   = threadIdx.x >> 5;
    const int n   = blockIdx.x * 32 + p;
    const int seg = M >> 3;

    float bd[8]; int bi[8];
    #pragma unroll
    for (int j = 0; j < 8; ++j) { bd[j] = 3.4e38f; bi[j] = 0; }

    auto ins = [&](float v, int id) {
        if (v < bd[7]) {
            bd[7] = v; bi[7] = id;
            #pragma unroll
            for (int r = 7; r >= 1; --r) {
                if (bd[r] < bd[r-1]) {
                    float td = bd[r]; bd[r] = bd[r-1]; bd[r-1] = td;
                    int   ti = bi[r]; bi[r] = bi[r-1]; bi[r-1] = ti;
                }
            }
        }
    };

    const float* col = D + (size_t)b * M * Npts + n + (size_t)(q * seg) * Npts;
    const int mbase = q * seg;
    #pragma unroll 2
    for (int m = 0; m < seg; m += 4) {
        float v0 = __ldg(col + (size_t)(m + 0) * Npts);
        float v1 = __ldg(col + (size_t)(m + 1) * Npts);
        float v2 = __ldg(col + (size_t)(m + 2) * Npts);
        float v3 = __ldg(col + (size_t)(m + 3) * Npts);
        ins(v0, mbase + m);
        ins(v1, mbase + m + 1);
        ins(v2, mbase + m + 2);
        ins(v3, mbase + m + 3);
    }
    #pragma unroll
    for (int j = 0; j < 8; ++j) { sd[p][q][j] = bd[j]; si[p][q][j] = bi[j]; }
    __syncthreads();

    if (threadIdx.x < 32) {
        const int pp = threadIdx.x;
        int ptr[8];
        #pragma unroll
        for (int j = 0; j < 8; ++j) ptr[j] = 0;
        float d8[8]; int i8[8];
        #pragma unroll
        for (int k = 0; k < 8; ++k) {
            float best = sd[pp][0][ptr[0]]; int bq = 0;
            #pragma unroll
            for (int j = 1; j < 8; ++j) {
                float vj = sd[pp][j][ptr[j]];
                if (vj < best) { best = vj; bq = j; }
            }
            d8[k] = best;
            i8[k] = si[pp][bq][ptr[bq]++];
        }
        float w[8], s = 0.f;
        #pragma unroll
        for (int j = 0; j < 8; ++j) { w[j] = 1.f / (d8[j] + 1e-8f); s += w[j]; }
        float inv = 1.f / (s + 1e-8f);
        const int nn = blockIdx.x * 32 + pp;
        size_t base = ((size_t)b * Npts + nn) * 8;
        #pragma unroll
        for (int j = 0; j < 8; ++j) { out_i[base + j] = i8[j]; out_w[base + j] = w[j] * inv; }
    }
}

// ---------------------------------------------------------------------------
// convert fp32 -> fp16
// ---------------------------------------------------------------------------
__global__ __launch_bounds__(256)
void cvt_x_half(const float* __restrict__ x, __half* __restrict__ hi, int n4)
{
    int i = blockIdx.x * 256 + threadIdx.x;
    if (i >= n4) return;
    float4 v = ((const float4*)x)[i];
    ((__half2*)hi)[i*2+0] = __halves2half2(__float2half_rn(v.x), __float2half_rn(v.y));
    ((__half2*)hi)[i*2+1] = __halves2half2(__float2half_rn(v.z), __float2half_rn(v.w));
}

// ---------------------------------------------------------------------------
// combine: v = ReLU(sc*(H[n] + sum_j w_j G[idx_j]) + bb) -> single fp16 plane
// ---------------------------------------------------------------------------
__global__ __launch_bounds__(256)
void combine_bn_relu(const float* __restrict__ H,    // [B][Np][640]
                     const float* __restrict__ G,    // [B][Ng][640]
                     const int*   __restrict__ knn_i,
                     const float* __restrict__ knn_w,
                     const float* __restrict__ bias,
                     const float* __restrict__ gamma,
                     const float* __restrict__ beta,
                     __half* __restrict__ Yh, int Np, int Ng)
{
    __shared__ float s_sc[640], s_bb[640];
    const float BNS = 0.99999500003749968f;   // 1/sqrt(1+1e-5)
    for (int c = threadIdx.x; c < 640; c += 256) {
        float sc = __ldg(gamma + c) * BNS;
        s_sc[c] = sc;
        s_bb[c] = sc * __ldg(bias + c) + __ldg(beta + c);
    }
    __syncthreads();
    const int b    = blockIdx.y;
    const int warp = threadIdx.x >> 5, lane = threadIdx.x & 31;
    const int n    = blockIdx.x * 8 + warp;
    const size_t pbase = (size_t)b * Np + n;

    int idx[8]; float w8[8];
    const int*   ip = knn_i + pbase * 8;
    const float* wp = knn_w + pbase * 8;
    #pragma unroll
    for (int j = 0; j < 8; ++j) { idx[j] = __ldg(ip + j); w8[j] = __ldg(wp + j); }

    const float* h = H + pbase * 640;
    float acc[20];
    #pragma unroll
    for (int r = 0; r < 20; ++r) acc[r] = __ldg(h + lane + 32 * r);
    #pragma unroll
    for (int j = 0; j < 8; ++j) {
        const float* g = G + ((size_t)b * Ng + idx[j]) * 640;
        const float wj = w8[j];
        #pragma unroll
        for (int r = 0; r < 20; ++r) acc[r] += wj * __ldg(g + lane + 32 * r);
    }
    #pragma unroll
    for (int r = 0; r < 20; ++r) {
        int c = lane + 32 * r;
        float v = fmaxf(s_sc[c] * acc[r] + s_bb[c], 0.f);
        Yh[pbase * 640 + c] = __float2half_rn(v);
    }
}

// ---------------------------------------------------------------------------
// mma.sync fp16 GEMM (R9 config):  D[o][n] = sum_k W[o][k] * X[n][k]
// Block 128x128, K-chunk 64, 512 threads = 4x4 warps, warp tile 32x32.
// 3-stage cp.async pipeline (2 planes/stage), one __syncthreads per chunk.
// Smem row stride 144 B: LDSM conflict-free (144 mod 128 = 16).
// mode: 0 = channel-major fp32 + BN+ReLU
//       1 = point-major fp16 + BN+ReLU
//       2 = point-major fp32 raw
// ---------------------------------------------------------------------------
#define PLANE_BYTES 18432              // 128 rows x 144 B
#define STAGE_BYTES (2 * PLANE_BYTES)  // W, X
#define GEMM_SMEM   (3 * STAGE_BYTES)  // 110592; epilogue (67584 B) reuses it

__global__ __launch_bounds__(512)
void gemm_mma(const __half* __restrict__ Wh, int ldW,
              const __half* __restrict__ Xh,
              float* __restrict__ Yf, __half* __restrict__ Yhp,
              const float* __restrict__ bias, const float* __restrict__ gamma,
              const float* __restrict__ beta,
              int K, int N, int O, int mode)
{
    extern __shared__ char dsm[];
    const uint32_t sbase = smem_u32_of(dsm);
    const int t = threadIdx.x, lane = t & 31, w = t >> 5;
    const int wm = w >> 2, wn = w & 3;
    const int b  = blockIdx.z;
    const int n0 = blockIdx.x * 128;
    const int o0 = blockIdx.y * 128;

    const __half* srcs[2];
    srcs[0] = Wh + (size_t)o0 * ldW;
    srcs[1] = Xh + ((size_t)b * N + n0) * K;
    int lds[2] = { ldW, K };

    float accm[2][4][4];
    #pragma unroll
    for (int i = 0; i < 2; ++i)
        #pragma unroll
        for (int j = 0; j < 4; ++j)
            #pragma unroll
            for (int e = 0; e < 4; ++e) accm[i][j][e] = 0.f;

    auto cp_stage = [&](int k0, int buf) {
        uint32_t sb = sbase + buf * STAGE_BYTES;
        #pragma unroll
        for (int pl = 0; pl < 2; ++pl) {
            #pragma unroll
            for (int u = 0; u < 2; ++u) {
                int idx = t * 2 + u;            // 0..1023
                int row = idx >> 3, c8 = idx & 7;
                cp16(sb + pl * PLANE_BYTES + row * 144 + c8 * 16,
                     srcs[pl] + (size_t)row * lds[pl] + k0 + c8 * 8);
            }
        }
        asm volatile("cp.async.commit_group;" ::: "memory");
    };

    const int g = lane >> 3;
    const int arow_off = (g & 1) * 8 + (lane & 7);
    const int acol_off = (g >> 1) * 8;
    const int brow_off = (g >> 1) * 8 + (lane & 7);
    const int bcol_off = (g & 1) * 8;

    const int nc = K >> 6;
    cp_stage(0, 0);
    if (nc > 1) cp_stage(64, 1);

    int buf = 0;
    for (int it = 0; it < nc; ++it) {
        if (it + 1 < nc) asm volatile("cp.async.wait_group 1;" ::: "memory");
        else             asm volatile("cp.async.wait_group 0;" ::: "memory");
        __syncthreads();
        if (it + 2 < nc) {
            int nb = buf + 2; if (nb >= 3) nb -= 3;
            cp_stage((it + 2) << 6, nb);
        }

        const uint32_t pA = sbase + buf * STAGE_BYTES;
        const uint32_t pB = pA + PLANE_BYTES;
        #pragma unroll
        for (int ks = 0; ks < 4; ++ks) {
            uint32_t ah[2][4];
            #pragma unroll
            for (int mt = 0; mt < 2; ++mt) {
                uint32_t ad = (uint32_t)(wm * 32 + mt * 16 + arow_off) * 144
                            + (uint32_t)(ks * 16 + acol_off) * 2;
                ldsm4(ah[mt], pA + ad);
            }
            #pragma unroll
            for (int np = 0; np < 2; ++np) {
                uint32_t bd = (uint32_t)(wn * 32 + np * 16 + brow_off) * 144
                            + (uint32_t)(ks * 16 + bcol_off) * 2;
                uint32_t bh[4];
                ldsm4(bh, pB + bd);
                #pragma unroll
                for (int mt = 0; mt < 2; ++mt)
                    #pragma unroll
                    for (int nj = 0; nj < 2; ++nj)
                        mma16816(accm[mt][np * 2 + nj], ah[mt], bh + nj * 2);
            }
        }
        ++buf; if (buf == 3) buf = 0;
    }
    __syncthreads();   // all MMA reads done before smem reuse

    // ---- epilogue through smem (stride 132 floats) ----
    float* smf = (float*)dsm;
    const int base_r = wm * 32 + (lane >> 2);
    const int base_c = wn * 32 + (lane & 3) * 2;
    #pragma unroll
    for (int mt = 0; mt < 2; ++mt)
        #pragma unroll
        for (int nt = 0; nt < 4; ++nt) {
            float v0 = accm[mt][nt][0];
            float v1 = accm[mt][nt][1];
            float v2 = accm[mt][nt][2];
            float v3 = accm[mt][nt][3];
            int r = base_r + mt * 16, c = base_c + (nt >> 1) * 16 + (nt & 1) * 8;
            if (mode == 0) {
                smf[r * 132 + c]           = v0;
                smf[r * 132 + c + 1]       = v1;
                smf[(r + 8) * 132 + c]     = v2;
                smf[(r + 8) * 132 + c + 1] = v3;
            } else {
                smf[c * 132 + r]           = v0;
                smf[(c + 1) * 132 + r]     = v1;
                smf[c * 132 + r + 8]       = v2;
                smf[(c + 1) * 132 + r + 8] = v3;
            }
        }
    __syncthreads();

    const float BNS = 0.99999500003749968f;
    if (mode == 0) {
        int o = t >> 2, nch = (t & 3) * 32;
        float sc = __ldg(gamma + o0 + o) * BNS;
        float bb = sc * __ldg(bias + o0 + o) + __ldg(beta + o0 + o);
        float* dst = Yf + ((size_t)b * O + o0 + o) * N + n0 + nch;
        #pragma unroll
        for (int j = 0; j < 32; j += 4) {
            float4 v;
            v.x = fmaxf(sc * smf[o * 132 + nch + j]     + bb, 0.f);
            v.y = fmaxf(sc * smf[o * 132 + nch + j + 1] + bb, 0.f);
            v.z = fmaxf(sc * smf[o * 132 + nch + j + 2] + bb, 0.f);
            v.w = fmaxf(sc * smf[o * 132 + nch + j + 3] + bb, 0.f);
            *(float4*)(dst + j) = v;
        }
    } else if (mode == 2) {
        int n = t >> 2, och = (t & 3) * 32;
        float* dst = Yf + ((size_t)b * N + n0 + n) * O + o0 + och;
        #pragma unroll
        for (int j = 0; j < 32; j += 4) {
            float4 v;
            v.x = smf[n * 132 + och + j];
            v.y = smf[n * 132 + och + j + 1];
            v.z = smf[n * 132 + och + j + 2];
            v.w = smf[n * 132 + och + j + 3];
            *(float4*)(dst + j) = v;
        }
    } else {
        int n = t >> 2, och = (t & 3) * 32;
        size_t off = ((size_t)b * N + n0 + n) * O + o0 + och;
        #pragma unroll
        for (int j0 = 0; j0 < 32; j0 += 8) {
            union { __half h[8]; uint4 u; } Hh;
            #pragma unroll
            for (int j = 0; j < 8; ++j) {
                int o = o0 + och + j0 + j;
                float sc = __ldg(gamma + o) * BNS;
                float bb = sc * __ldg(bias + o) + __ldg(beta + o);
                float v = fmaxf(sc * smf[n * 132 + och + j0 + j] + bb, 0.f);
                Hh.h[j] = __float2half_rn(v);
            }
            *(uint4*)(Yhp + off + j0) = Hh.u;
        }
    }
}

// ---------------------------------------------------------------------------
extern "C" void kernel_launch(void* const* d_in, const int* in_sizes, int n_in,
                              void* d_out, int out_size)
{
    const float* radar = (const float*)d_in[0];
    const float* l1f   = (const float*)d_in[1];
    const float* l2f   = (const float*)d_in[2];
    const float* l0_l1 = (const float*)d_in[3];
    const float* l1_l2 = (const float*)d_in[4];
    const float* w21a  = (const float*)d_in[5];
    const float* b21a  = (const float*)d_in[6];
    const float* g21a  = (const float*)d_in[7];
    const float* be21a = (const float*)d_in[8];
    const float* w21b  = (const float*)d_in[9];
    const float* b21b  = (const float*)d_in[10];
    const float* g21b  = (const float*)d_in[11];
    const float* be21b = (const float*)d_in[12];
    const float* w10a  = (const float*)d_in[13];
    const float* b10a  = (const float*)d_in[14];
    const float* g10a  = (const float*)d_in[15];
    const float* be10a = (const float*)d_in[16];
    const float* w10b  = (const float*)d_in[17];
    const float* b10b  = (const float*)d_in[18];
    const float* g10b  = (const float*)d_in[19];
    const float* be10b = (const float*)d_in[20];

    cudaFuncSetAttribute(gemm_mma, cudaFuncAttributeMaxDynamicSharedMemorySize, GEMM_SMEM);

    __half *l1h,*l2h,*rdh;
    __half *w21ah,*w21bh,*w10ah,*w10bh;
    __half *Y1h,*Fh,*Y3h;
    float *G2,*H1,*G,*Hr,*w1,*w0;
    int *i1,*i0;
    cudaGetSymbolAddress((void**)&l1h, g_l1h);
    cudaGetSymbolAddress((void**)&l2h, g_l2h);
    cudaGetSymbolAddress((void**)&rdh, g_rdh);
    cudaGetSymbolAddress((void**)&w21ah, g_w21ah);
    cudaGetSymbolAddress((void**)&w21bh, g_w21bh);
    cudaGetSymbolAddress((void**)&w10ah, g_w10ah);
    cudaGetSymbolAddress((void**)&w10bh, g_w10bh);
    cudaGetSymbolAddress((void**)&Y1h, g_Y1h);
    cudaGetSymbolAddress((void**)&Fh,  g_Fh);
    cudaGetSymbolAddress((void**)&Y3h, g_Y3h);
    cudaGetSymbolAddress((void**)&G2, g_G2);     cudaGetSymbolAddress((void**)&H1, g_H1);
    cudaGetSymbolAddress((void**)&G,  g_G);      cudaGetSymbolAddress((void**)&Hr, g_Hr);
    cudaGetSymbolAddress((void**)&i1, g_i1);     cudaGetSymbolAddress((void**)&w1, g_w1);
    cudaGetSymbolAddress((void**)&i0, g_i0);     cudaGetSymbolAddress((void**)&w0, g_w0);

    // positions 5 AND 6 are gemm_mma so the ncu window lands on a GEMM.
    cvt_x_half<<<(640*320/4 + 255)/256, 256>>>(w21a, w21ah, 640*320/4);            // 1
    cvt_x_half<<<(B_*N1_*128/4 + 255)/256, 256>>>(l1f, l1h, B_*N1_*128/4);         // 2
    cvt_x_half<<<(B_*N2_*192/4 + 255)/256, 256>>>(l2f, l2h, B_*N2_*192/4);         // 3
    knn_topk<<<dim3(N1_/32, B_), 256>>>(l1_l2, N2_, N1_, i1, w1);                  // 4
    gemm_mma<<<dim3(N1_/128, 5, B_), 512, GEMM_SMEM>>>(w21ah, 320, l1h,            // 5
        H1, nullptr, nullptr, nullptr, nullptr, 128, N1_, 640, 2);
    gemm_mma<<<dim3(N2_/128, 5, B_), 512, GEMM_SMEM>>>(w21ah+128, 320, l2h,        // 6
        G2, nullptr, nullptr, nullptr, nullptr, 192, N2_, 640, 2);
    knn_topk<<<dim3(N0_/32, B_), 256>>>(l0_l1, N1_, N0_, i0, w0);                  // 7
    combine_bn_relu<<<dim3(N1_/8, B_), 256>>>(H1, G2, i1, w1, b21a, g21a, be21a, Y1h, N1_, N2_);

    cvt_x_half<<<(640*640/4 + 255)/256, 256>>>(w21b, w21bh, 640*640/4);
    gemm_mma<<<dim3(N1_/128, 5, B_), 512, GEMM_SMEM>>>(w21bh, 640, Y1h,
        nullptr, Fh, b21b, g21b, be21b, 640, N1_, 640, 1);

    cvt_x_half<<<(640*704/4 + 255)/256, 256>>>(w10a, w10ah, 640*704/4);
    cvt_x_half<<<(B_*N0_*64/4 + 255)/256, 256>>>(radar, rdh, B_*N0_*64/4);
    gemm_mma<<<dim3(N1_/128, 5, B_), 512, GEMM_SMEM>>>(w10ah+64, 704, Fh,
        G, nullptr, nullptr, nullptr, nullptr, 640, N1_, 640, 2);
    gemm_mma<<<dim3(N0_/128, 5, B_), 512, GEMM_SMEM>>>(w10ah, 704, rdh,
        Hr, nullptr, nullptr, nullptr, nullptr, 64, N0_, 640, 2);
    combine_bn_relu<<<dim3(N0_/8, B_), 256>>>(Hr, G, i0, w0, b10a, g10a, be10a, Y3h, N0_, N1_);

    cvt_x_half<<<(768*640/4 + 255)/256, 256>>>(w10b, w10bh, 768*640/4);
    gemm_mma<<<dim3(N0_/128, 6, B_), 512, GEMM_SMEM>>>(w10bh, 640, Y3h,
        (float*)d_out, nullptr, b10b, g10b, be10b, 640, N0_, 768, 0);
}

// round 13
// speedup vs baseline: 1.4930x; 1.1021x over previous
#include <cuda_runtime.h>
#include <cuda_fp16.h>
#include <cstdint>
#include <cstddef>

// ---------------------------------------------------------------------------
// FeaturePropogate via mma.sync fp16 (plain sm_103 PTX):
//   - interp pushed through first MLP layer (W*concat == W_a*feat + interp(W_b*F))
//   - GEMMs: fp16 mma.sync, fp32 accum (R9 config: 128x128, K-chunk 64, 3-stage)
//   - KNN: 8 segments/point, 4-wide batched scan, 8-way merge (R11 config)
//   - NEW: all point-major intermediates (H1,G2,G,Hr) stored fp16; combine
//     reads/writes half2 (halves ~240 MB of fp32 DRAM traffic)
// ---------------------------------------------------------------------------

#define B_     4
#define N0_    8192
#define N1_    2048
#define N2_    512

// ---- device scratch (no allocation allowed) ----
__device__ __half g_l1h[(size_t)B_*N1_*128];
__device__ __half g_l2h[(size_t)B_*N2_*192];
__device__ __half g_rdh[(size_t)B_*N0_*64];
__device__ __half g_w21ah[640*320];
__device__ __half g_w21bh[640*640];
__device__ __half g_w10ah[640*704];
__device__ __half g_w10bh[768*640];
__device__ __half g_Y1h[(size_t)B_*N1_*640];
__device__ __half g_Fh [(size_t)B_*N1_*640];
__device__ __half g_Y3h[(size_t)B_*N0_*640];
__device__ __half g_G2[(size_t)B_*N2_*640];
__device__ __half g_H1[(size_t)B_*N1_*640];
__device__ __half g_G [(size_t)B_*N1_*640];
__device__ __half g_Hr[(size_t)B_*N0_*640];
__device__ int   g_i1[(size_t)B_*N1_*8];
__device__ float g_w1[(size_t)B_*N1_*8];
__device__ int   g_i0[(size_t)B_*N0_*8];
__device__ float g_w0[(size_t)B_*N0_*8];

__device__ __forceinline__ uint32_t smem_u32_of(const void* p) {
    uint32_t a;
    asm("{ .reg .u64 t; cvta.to.shared.u64 t, %1; cvt.u32.u64 %0, t; }" : "=r"(a) : "l"(p));
    return a;
}
__device__ __forceinline__ void ldsm4(uint32_t* r, uint32_t addr) {
    asm volatile("ldmatrix.sync.aligned.m8n8.x4.shared.b16 {%0,%1,%2,%3}, [%4];"
                 : "=r"(r[0]), "=r"(r[1]), "=r"(r[2]), "=r"(r[3]) : "r"(addr));
}
__device__ __forceinline__ void mma16816(float* d, const uint32_t* a, const uint32_t* b) {
    asm volatile(
        "mma.sync.aligned.m16n8k16.row.col.f32.f16.f16.f32 "
        "{%0,%1,%2,%3}, {%4,%5,%6,%7}, {%8,%9}, {%0,%1,%2,%3};"
        : "+f"(d[0]), "+f"(d[1]), "+f"(d[2]), "+f"(d[3])
        : "r"(a[0]), "r"(a[1]), "r"(a[2]), "r"(a[3]), "r"(b[0]), "r"(b[1]));
}
__device__ __forceinline__ void cp16(uint32_t saddr, const void* gaddr) {
    asm volatile("cp.async.cg.shared.global [%0], [%1], 16;" :: "r"(saddr), "l"(gaddr));
}

// ---------------------------------------------------------------------------
// KNN top-8 (R11 config): 256 threads = 32 points x 8 segments.
// ---------------------------------------------------------------------------
__global__ __launch_bounds__(256)
void knn_topk(const float* __restrict__ D, int M, int Npts,
              int* __restrict__ out_i, float* __restrict__ out_w)
{
    __shared__ float sd[32][8][8];
    __shared__ int   si[32][8][8];
    const int b   = blockIdx.y;
    const int p   = threadIdx.x & 31;
    const int q   = threadIdx.x >> 5;
    const int n   = blockIdx.x * 32 + p;
    const int seg = M >> 3;

    float bd[8]; int bi[8];
    #pragma unroll
    for (int j = 0; j < 8; ++j) { bd[j] = 3.4e38f; bi[j] = 0; }

    auto ins = [&](float v, int id) {
        if (v < bd[7]) {
            bd[7] = v; bi[7] = id;
            #pragma unroll
            for (int r = 7; r >= 1; --r) {
                if (bd[r] < bd[r-1]) {
                    float td = bd[r]; bd[r] = bd[r-1]; bd[r-1] = td;
                    int   ti = bi[r]; bi[r] = bi[r-1]; bi[r-1] = ti;
                }
            }
        }
    };

    const float* col = D + (size_t)b * M * Npts + n + (size_t)(q * seg) * Npts;
    const int mbase = q * seg;
    #pragma unroll 2
    for (int m = 0; m < seg; m += 4) {
        float v0 = __ldg(col + (size_t)(m + 0) * Npts);
        float v1 = __ldg(col + (size_t)(m + 1) * Npts);
        float v2 = __ldg(col + (size_t)(m + 2) * Npts);
        float v3 = __ldg(col + (size_t)(m + 3) * Npts);
        ins(v0, mbase + m);
        ins(v1, mbase + m + 1);
        ins(v2, mbase + m + 2);
        ins(v3, mbase + m + 3);
    }
    #pragma unroll
    for (int j = 0; j < 8; ++j) { sd[p][q][j] = bd[j]; si[p][q][j] = bi[j]; }
    __syncthreads();

    if (threadIdx.x < 32) {
        const int pp = threadIdx.x;
        int ptr[8];
        #pragma unroll
        for (int j = 0; j < 8; ++j) ptr[j] = 0;
        float d8[8]; int i8[8];
        #pragma unroll
        for (int k = 0; k < 8; ++k) {
            float best = sd[pp][0][ptr[0]]; int bq = 0;
            #pragma unroll
            for (int j = 1; j < 8; ++j) {
                float vj = sd[pp][j][ptr[j]];
                if (vj < best) { best = vj; bq = j; }
            }
            d8[k] = best;
            i8[k] = si[pp][bq][ptr[bq]++];
        }
        float w[8], s = 0.f;
        #pragma unroll
        for (int j = 0; j < 8; ++j) { w[j] = 1.f / (d8[j] + 1e-8f); s += w[j]; }
        float inv = 1.f / (s + 1e-8f);
        const int nn = blockIdx.x * 32 + pp;
        size_t base = ((size_t)b * Npts + nn) * 8;
        #pragma unroll
        for (int j = 0; j < 8; ++j) { out_i[base + j] = i8[j]; out_w[base + j] = w[j] * inv; }
    }
}

// ---------------------------------------------------------------------------
// convert fp32 -> fp16
// ---------------------------------------------------------------------------
__global__ __launch_bounds__(256)
void cvt_x_half(const float* __restrict__ x, __half* __restrict__ hi, int n4)
{
    int i = blockIdx.x * 256 + threadIdx.x;
    if (i >= n4) return;
    float4 v = ((const float4*)x)[i];
    ((__half2*)hi)[i*2+0] = __halves2half2(__float2half_rn(v.x), __float2half_rn(v.y));
    ((__half2*)hi)[i*2+1] = __halves2half2(__float2half_rn(v.z), __float2half_rn(v.w));
}

// ---------------------------------------------------------------------------
// combine: v = ReLU(sc*(H[n] + sum_j w_j G[idx_j]) + bb), fp16 in / fp16 out.
// Lane handles 10 half2 pairs: pair index c2 = lane + 32*r, r < 10.
// ---------------------------------------------------------------------------
__global__ __launch_bounds__(256)
void combine_bn_relu(const __half* __restrict__ H,    // [B][Np][640] fp16
                     const __half* __restrict__ G,    // [B][Ng][640] fp16
                     const int*   __restrict__ knn_i,
                     const float* __restrict__ knn_w,
                     const float* __restrict__ bias,
                     const float* __restrict__ gamma,
                     const float* __restrict__ beta,
                     __half* __restrict__ Yh, int Np, int Ng)
{
    __shared__ float s_sc[640], s_bb[640];
    const float BNS = 0.99999500003749968f;   // 1/sqrt(1+1e-5)
    for (int c = threadIdx.x; c < 640; c += 256) {
        float sc = __ldg(gamma + c) * BNS;
        s_sc[c] = sc;
        s_bb[c] = sc * __ldg(bias + c) + __ldg(beta + c);
    }
    __syncthreads();
    const int b    = blockIdx.y;
    const int warp = threadIdx.x >> 5, lane = threadIdx.x & 31;
    const int n    = blockIdx.x * 8 + warp;
    const size_t pbase = (size_t)b * Np + n;

    int idx[8]; float w8[8];
    const int*   ip = knn_i + pbase * 8;
    const float* wp = knn_w + pbase * 8;
    #pragma unroll
    for (int j = 0; j < 8; ++j) { idx[j] = __ldg(ip + j); w8[j] = __ldg(wp + j); }

    const __half2* h2 = (const __half2*)(H + pbase * 640);
    float2 acc[10];
    #pragma unroll
    for (int r = 0; r < 10; ++r) acc[r] = __half22float2(__ldg(h2 + lane + 32 * r));
    #pragma unroll
    for (int j = 0; j < 8; ++j) {
        const __half2* g2 = (const __half2*)(G + ((size_t)b * Ng + idx[j]) * 640);
        const float wj = w8[j];
        #pragma unroll
        for (int r = 0; r < 10; ++r) {
            float2 gv = __half22float2(__ldg(g2 + lane + 32 * r));
            acc[r].x += wj * gv.x;
            acc[r].y += wj * gv.y;
        }
    }
    __half2* y2 = (__half2*)(Yh + pbase * 640);
    #pragma unroll
    for (int r = 0; r < 10; ++r) {
        int c = (lane + 32 * r) * 2;
        float vx = fmaxf(s_sc[c]     * acc[r].x + s_bb[c],     0.f);
        float vy = fmaxf(s_sc[c + 1] * acc[r].y + s_bb[c + 1], 0.f);
        y2[lane + 32 * r] = __floats2half2_rn(vx, vy);
    }
}

// ---------------------------------------------------------------------------
// mma.sync fp16 GEMM (R9 config):  D[o][n] = sum_k W[o][k] * X[n][k]
// Block 128x128, K-chunk 64, 512 threads = 4x4 warps, warp tile 32x32.
// 3-stage cp.async pipeline, one __syncthreads per chunk. Stride 144 B.
// mode: 0 = channel-major fp32 + BN+ReLU (final output)
//       1 = point-major fp16 + BN+ReLU
//       2 = point-major fp16 raw (no BN/ReLU)
// ---------------------------------------------------------------------------
#define PLANE_BYTES 18432              // 128 rows x 144 B
#define STAGE_BYTES (2 * PLANE_BYTES)  // W, X
#define GEMM_SMEM   (3 * STAGE_BYTES)  // 110592; epilogue (67584 B) reuses it

__global__ __launch_bounds__(512)
void gemm_mma(const __half* __restrict__ Wh, int ldW,
              const __half* __restrict__ Xh,
              float* __restrict__ Yf, __half* __restrict__ Yhp,
              const float* __restrict__ bias, const float* __restrict__ gamma,
              const float* __restrict__ beta,
              int K, int N, int O, int mode)
{
    extern __shared__ char dsm[];
    const uint32_t sbase = smem_u32_of(dsm);
    const int t = threadIdx.x, lane = t & 31, w = t >> 5;
    const int wm = w >> 2, wn = w & 3;
    const int b  = blockIdx.z;
    const int n0 = blockIdx.x * 128;
    const int o0 = blockIdx.y * 128;

    const __half* srcs[2];
    srcs[0] = Wh + (size_t)o0 * ldW;
    srcs[1] = Xh + ((size_t)b * N + n0) * K;
    int lds[2] = { ldW, K };

    float accm[2][4][4];
    #pragma unroll
    for (int i = 0; i < 2; ++i)
        #pragma unroll
        for (int j = 0; j < 4; ++j)
            #pragma unroll
            for (int e = 0; e < 4; ++e) accm[i][j][e] = 0.f;

    auto cp_stage = [&](int k0, int buf) {
        uint32_t sb = sbase + buf * STAGE_BYTES;
        #pragma unroll
        for (int pl = 0; pl < 2; ++pl) {
            #pragma unroll
            for (int u = 0; u < 2; ++u) {
                int idx = t * 2 + u;            // 0..1023
                int row = idx >> 3, c8 = idx & 7;
                cp16(sb + pl * PLANE_BYTES + row * 144 + c8 * 16,
                     srcs[pl] + (size_t)row * lds[pl] + k0 + c8 * 8);
            }
        }
        asm volatile("cp.async.commit_group;" ::: "memory");
    };

    const int g = lane >> 3;
    const int arow_off = (g & 1) * 8 + (lane & 7);
    const int acol_off = (g >> 1) * 8;
    const int brow_off = (g >> 1) * 8 + (lane & 7);
    const int bcol_off = (g & 1) * 8;

    const int nc = K >> 6;
    cp_stage(0, 0);
    if (nc > 1) cp_stage(64, 1);

    int buf = 0;
    for (int it = 0; it < nc; ++it) {
        if (it + 1 < nc) asm volatile("cp.async.wait_group 1;" ::: "memory");
        else             asm volatile("cp.async.wait_group 0;" ::: "memory");
        __syncthreads();
        if (it + 2 < nc) {
            int nb = buf + 2; if (nb >= 3) nb -= 3;
            cp_stage((it + 2) << 6, nb);
        }

        const uint32_t pA = sbase + buf * STAGE_BYTES;
        const uint32_t pB = pA + PLANE_BYTES;
        #pragma unroll
        for (int ks = 0; ks < 4; ++ks) {
            uint32_t ah[2][4];
            #pragma unroll
            for (int mt = 0; mt < 2; ++mt) {
                uint32_t ad = (uint32_t)(wm * 32 + mt * 16 + arow_off) * 144
                            + (uint32_t)(ks * 16 + acol_off) * 2;
                ldsm4(ah[mt], pA + ad);
            }
            #pragma unroll
            for (int np = 0; np < 2; ++np) {
                uint32_t bd = (uint32_t)(wn * 32 + np * 16 + brow_off) * 144
                            + (uint32_t)(ks * 16 + bcol_off) * 2;
                uint32_t bh[4];
                ldsm4(bh, pB + bd);
                #pragma unroll
                for (int mt = 0; mt < 2; ++mt)
                    #pragma unroll
                    for (int nj = 0; nj < 2; ++nj)
                        mma16816(accm[mt][np * 2 + nj], ah[mt], bh + nj * 2);
            }
        }
        ++buf; if (buf == 3) buf = 0;
    }
    __syncthreads();   // all MMA reads done before smem reuse

    // ---- epilogue through smem (stride 132 floats) ----
    float* smf = (float*)dsm;
    const int base_r = wm * 32 + (lane >> 2);
    const int base_c = wn * 32 + (lane & 3) * 2;
    #pragma unroll
    for (int mt = 0; mt < 2; ++mt)
        #pragma unroll
        for (int nt = 0; nt < 4; ++nt) {
            float v0 = accm[mt][nt][0];
            float v1 = accm[mt][nt][1];
            float v2 = accm[mt][nt][2];
            float v3 = accm[mt][nt][3];
            int r = base_r + mt * 16, c = base_c + (nt >> 1) * 16 + (nt & 1) * 8;
            if (mode == 0) {
                smf[r * 132 + c]           = v0;
                smf[r * 132 + c + 1]       = v1;
                smf[(r + 8) * 132 + c]     = v2;
                smf[(r + 8) * 132 + c + 1] = v3;
            } else {
                smf[c * 132 + r]           = v0;
                smf[(c + 1) * 132 + r]     = v1;
                smf[c * 132 + r + 8]       = v2;
                smf[(c + 1) * 132 + r + 8] = v3;
            }
        }
    __syncthreads();

    const float BNS = 0.99999500003749968f;
    if (mode == 0) {
        int o = t >> 2, nch = (t & 3) * 32;
        float sc = __ldg(gamma + o0 + o) * BNS;
        float bb = sc * __ldg(bias + o0 + o) + __ldg(beta + o0 + o);
        float* dst = Yf + ((size_t)b * O + o0 + o) * N + n0 + nch;
        #pragma unroll
        for (int j = 0; j < 32; j += 4) {
            float4 v;
            v.x = fmaxf(sc * smf[o * 132 + nch + j]     + bb, 0.f);
            v.y = fmaxf(sc * smf[o * 132 + nch + j + 1] + bb, 0.f);
            v.z = fmaxf(sc * smf[o * 132 + nch + j + 2] + bb, 0.f);
            v.w = fmaxf(sc * smf[o * 132 + nch + j + 3] + bb, 0.f);
            *(float4*)(dst + j) = v;
        }
    } else {
        int n = t >> 2, och = (t & 3) * 32;
        size_t off = ((size_t)b * N + n0 + n) * O + o0 + och;
        #pragma unroll
        for (int j0 = 0; j0 < 32; j0 += 8) {
            union { __half h[8]; uint4 u; } Hh;
            #pragma unroll
            for (int j = 0; j < 8; ++j) {
                float v = smf[n * 132 + och + j0 + j];
                if (mode == 1) {
                    int o = o0 + och + j0 + j;
                    float sc = __ldg(gamma + o) * BNS;
                    float bb = sc * __ldg(bias + o) + __ldg(beta + o);
                    v = fmaxf(sc * v + bb, 0.f);
                }
                Hh.h[j] = __float2half_rn(v);
            }
            *(uint4*)(Yhp + off + j0) = Hh.u;
        }
    }
}

// ---------------------------------------------------------------------------
extern "C" void kernel_launch(void* const* d_in, const int* in_sizes, int n_in,
                              void* d_out, int out_size)
{
    const float* radar = (const float*)d_in[0];
    const float* l1f   = (const float*)d_in[1];
    const float* l2f   = (const float*)d_in[2];
    const float* l0_l1 = (const float*)d_in[3];
    const float* l1_l2 = (const float*)d_in[4];
    const float* w21a  = (const float*)d_in[5];
    const float* b21a  = (const float*)d_in[6];
    const float* g21a  = (const float*)d_in[7];
    const float* be21a = (const float*)d_in[8];
    const float* w21b  = (const float*)d_in[9];
    const float* b21b  = (const float*)d_in[10];
    const float* g21b  = (const float*)d_in[11];
    const float* be21b = (const float*)d_in[12];
    const float* w10a  = (const float*)d_in[13];
    const float* b10a  = (const float*)d_in[14];
    const float* g10a  = (const float*)d_in[15];
    const float* be10a = (const float*)d_in[16];
    const float* w10b  = (const float*)d_in[17];
    const float* b10b  = (const float*)d_in[18];
    const float* g10b  = (const float*)d_in[19];
    const float* be10b = (const float*)d_in[20];

    cudaFuncSetAttribute(gemm_mma, cudaFuncAttributeMaxDynamicSharedMemorySize, GEMM_SMEM);

    __half *l1h,*l2h,*rdh;
    __half *w21ah,*w21bh,*w10ah,*w10bh;
    __half *Y1h,*Fh,*Y3h,*G2,*H1,*G,*Hr;
    float *w1,*w0;
    int *i1,*i0;
    cudaGetSymbolAddress((void**)&l1h, g_l1h);
    cudaGetSymbolAddress((void**)&l2h, g_l2h);
    cudaGetSymbolAddress((void**)&rdh, g_rdh);
    cudaGetSymbolAddress((void**)&w21ah, g_w21ah);
    cudaGetSymbolAddress((void**)&w21bh, g_w21bh);
    cudaGetSymbolAddress((void**)&w10ah, g_w10ah);
    cudaGetSymbolAddress((void**)&w10bh, g_w10bh);
    cudaGetSymbolAddress((void**)&Y1h, g_Y1h);
    cudaGetSymbolAddress((void**)&Fh,  g_Fh);
    cudaGetSymbolAddress((void**)&Y3h, g_Y3h);
    cudaGetSymbolAddress((void**)&G2, g_G2);     cudaGetSymbolAddress((void**)&H1, g_H1);
    cudaGetSymbolAddress((void**)&G,  g_G);      cudaGetSymbolAddress((void**)&Hr, g_Hr);
    cudaGetSymbolAddress((void**)&i1, g_i1);     cudaGetSymbolAddress((void**)&w1, g_w1);
    cudaGetSymbolAddress((void**)&i0, g_i0);     cudaGetSymbolAddress((void**)&w0, g_w0);

    // positions 5 AND 6 are gemm_mma so the ncu window lands on a GEMM.
    cvt_x_half<<<(640*320/4 + 255)/256, 256>>>(w21a, w21ah, 640*320/4);            // 1
    cvt_x_half<<<(B_*N1_*128/4 + 255)/256, 256>>>(l1f, l1h, B_*N1_*128/4);         // 2
    cvt_x_half<<<(B_*N2_*192/4 + 255)/256, 256>>>(l2f, l2h, B_*N2_*192/4);         // 3
    knn_topk<<<dim3(N1_/32, B_), 256>>>(l1_l2, N2_, N1_, i1, w1);                  // 4
    gemm_mma<<<dim3(N1_/128, 5, B_), 512, GEMM_SMEM>>>(w21ah, 320, l1h,            // 5
        nullptr, H1, nullptr, nullptr, nullptr, 128, N1_, 640, 2);
    gemm_mma<<<dim3(N2_/128, 5, B_), 512, GEMM_SMEM>>>(w21ah+128, 320, l2h,        // 6
        nullptr, G2, nullptr, nullptr, nullptr, 192, N2_, 640, 2);
    knn_topk<<<dim3(N0_/32, B_), 256>>>(l0_l1, N1_, N0_, i0, w0);                  // 7
    combine_bn_relu<<<dim3(N1_/8, B_), 256>>>(H1, G2, i1, w1, b21a, g21a, be21a, Y1h, N1_, N2_);

    cvt_x_half<<<(640*640/4 + 255)/256, 256>>>(w21b, w21bh, 640*640/4);
    gemm_mma<<<dim3(N1_/128, 5, B_), 512, GEMM_SMEM>>>(w21bh, 640, Y1h,
        nullptr, Fh, b21b, g21b, be21b, 640, N1_, 640, 1);

    cvt_x_half<<<(640*704/4 + 255)/256, 256>>>(w10a, w10ah, 640*704/4);
    cvt_x_half<<<(B_*N0_*64/4 + 255)/256, 256>>>(radar, rdh, B_*N0_*64/4);
    gemm_mma<<<dim3(N1_/128, 5, B_), 512, GEMM_SMEM>>>(w10ah+64, 704, Fh,
        nullptr, G, nullptr, nullptr, nullptr, 640, N1_, 640, 2);
    gemm_mma<<<dim3(N0_/128, 5, B_), 512, GEMM_SMEM>>>(w10ah, 704, rdh,
        nullptr, Hr, nullptr, nullptr, nullptr, 64, N0_, 640, 2);
    combine_bn_relu<<<dim3(N0_/8, B_), 256>>>(Hr, G, i0, w0, b10a, g10a, be10a, Y3h, N0_, N1_);

    cvt_x_half<<<(768*640/4 + 255)/256, 256>>>(w10b, w10bh, 768*640/4);
    gemm_mma<<<dim3(N0_/128, 6, B_), 512, GEMM_SMEM>>>(w10bh, 640, Y3h,
        (float*)d_out, nullptr, b10b, g10b, be10b, 640, N0_, 768, 0);
}

// round 14
// speedup vs baseline: 1.6053x; 1.0752x over previous
#include <cuda_runtime.h>
#include <cuda_fp16.h>
#include <cstdint>
#include <cstddef>

// ---------------------------------------------------------------------------
// FeaturePropogate via mma.sync fp16 (plain sm_103 PTX):
//   - interp pushed through first MLP layer (W*concat == W_a*feat + interp(W_b*F))
//   - GEMMs: fp16 mma.sync, fp32 accum (128x128, K-chunk 64, 3-stage)  [R12]
//   - KNN: 8 segments/point, batched scan, 8-way merge                 [R12]
//   - fp16 point-major intermediates everywhere                        [R12]
//   - NEW: KNN chain on a side stream (parallel graph branch); all 7
//     fp32->fp16 converts fused into one kernel
// ---------------------------------------------------------------------------

#define B_     4
#define N0_    8192
#define N1_    2048
#define N2_    512

// ---- device scratch (no allocation allowed) ----
__device__ __half g_l1h[(size_t)B_*N1_*128];
__device__ __half g_l2h[(size_t)B_*N2_*192];
__device__ __half g_rdh[(size_t)B_*N0_*64];
__device__ __half g_w21ah[640*320];
__device__ __half g_w21bh[640*640];
__device__ __half g_w10ah[640*704];
__device__ __half g_w10bh[768*640];
__device__ __half g_Y1h[(size_t)B_*N1_*640];
__device__ __half g_Fh [(size_t)B_*N1_*640];
__device__ __half g_Y3h[(size_t)B_*N0_*640];
__device__ __half g_G2[(size_t)B_*N2_*640];
__device__ __half g_H1[(size_t)B_*N1_*640];
__device__ __half g_G [(size_t)B_*N1_*640];
__device__ __half g_Hr[(size_t)B_*N0_*640];
__device__ int   g_i1[(size_t)B_*N1_*8];
__device__ float g_w1[(size_t)B_*N1_*8];
__device__ int   g_i0[(size_t)B_*N0_*8];
__device__ float g_w0[(size_t)B_*N0_*8];

__device__ __forceinline__ uint32_t smem_u32_of(const void* p) {
    uint32_t a;
    asm("{ .reg .u64 t; cvta.to.shared.u64 t, %1; cvt.u32.u64 %0, t; }" : "=r"(a) : "l"(p));
    return a;
}
__device__ __forceinline__ void ldsm4(uint32_t* r, uint32_t addr) {
    asm volatile("ldmatrix.sync.aligned.m8n8.x4.shared.b16 {%0,%1,%2,%3}, [%4];"
                 : "=r"(r[0]), "=r"(r[1]), "=r"(r[2]), "=r"(r[3]) : "r"(addr));
}
__device__ __forceinline__ void mma16816(float* d, const uint32_t* a, const uint32_t* b) {
    asm volatile(
        "mma.sync.aligned.m16n8k16.row.col.f32.f16.f16.f32 "
        "{%0,%1,%2,%3}, {%4,%5,%6,%7}, {%8,%9}, {%0,%1,%2,%3};"
        : "+f"(d[0]), "+f"(d[1]), "+f"(d[2]), "+f"(d[3])
        : "r"(a[0]), "r"(a[1]), "r"(a[2]), "r"(a[3]), "r"(b[0]), "r"(b[1]));
}
__device__ __forceinline__ void cp16(uint32_t saddr, const void* gaddr) {
    asm volatile("cp.async.cg.shared.global [%0], [%1], 16;" :: "r"(saddr), "l"(gaddr));
}

// ---------------------------------------------------------------------------
// KNN top-8 (R11/R12 config): 256 threads = 32 points x 8 segments.
// ---------------------------------------------------------------------------
__global__ __launch_bounds__(256)
void knn_topk(const float* __restrict__ D, int M, int Npts,
              int* __restrict__ out_i, float* __restrict__ out_w)
{
    __shared__ float sd[32][8][8];
    __shared__ int   si[32][8][8];
    const int b   = blockIdx.y;
    const int p   = threadIdx.x & 31;
    const int q   = threadIdx.x >> 5;
    const int n   = blockIdx.x * 32 + p;
    const int seg = M >> 3;

    float bd[8]; int bi[8];
    #pragma unroll
    for (int j = 0; j < 8; ++j) { bd[j] = 3.4e38f; bi[j] = 0; }

    auto ins = [&](float v, int id) {
        if (v < bd[7]) {
            bd[7] = v; bi[7] = id;
            #pragma unroll
            for (int r = 7; r >= 1; --r) {
                if (bd[r] < bd[r-1]) {
                    float td = bd[r]; bd[r] = bd[r-1]; bd[r-1] = td;
                    int   ti = bi[r]; bi[r] = bi[r-1]; bi[r-1] = ti;
                }
            }
        }
    };

    const float* col = D + (size_t)b * M * Npts + n + (size_t)(q * seg) * Npts;
    const int mbase = q * seg;
    #pragma unroll 2
    for (int m = 0; m < seg; m += 4) {
        float v0 = __ldg(col + (size_t)(m + 0) * Npts);
        float v1 = __ldg(col + (size_t)(m + 1) * Npts);
        float v2 = __ldg(col + (size_t)(m + 2) * Npts);
        float v3 = __ldg(col + (size_t)(m + 3) * Npts);
        ins(v0, mbase + m);
        ins(v1, mbase + m + 1);
        ins(v2, mbase + m + 2);
        ins(v3, mbase + m + 3);
    }
    #pragma unroll
    for (int j = 0; j < 8; ++j) { sd[p][q][j] = bd[j]; si[p][q][j] = bi[j]; }
    __syncthreads();

    if (threadIdx.x < 32) {
        const int pp = threadIdx.x;
        int ptr[8];
        #pragma unroll
        for (int j = 0; j < 8; ++j) ptr[j] = 0;
        float d8[8]; int i8[8];
        #pragma unroll
        for (int k = 0; k < 8; ++k) {
            float best = sd[pp][0][ptr[0]]; int bq = 0;
            #pragma unroll
            for (int j = 1; j < 8; ++j) {
                float vj = sd[pp][j][ptr[j]];
                if (vj < best) { best = vj; bq = j; }
            }
            d8[k] = best;
            i8[k] = si[pp][bq][ptr[bq]++];
        }
        float w[8], s = 0.f;
        #pragma unroll
        for (int j = 0; j < 8; ++j) { w[j] = 1.f / (d8[j] + 1e-8f); s += w[j]; }
        float inv = 1.f / (s + 1e-8f);
        const int nn = blockIdx.x * 32 + pp;
        size_t base = ((size_t)b * Npts + nn) * 8;
        #pragma unroll
        for (int j = 0; j < 8; ++j) { out_i[base + j] = i8[j]; out_w[base + j] = w[j] * inv; }
    }
}

// ---------------------------------------------------------------------------
// fused converts: all 7 fp32 -> fp16 tensors in one launch.
// Segment boundaries in float4 units.
// ---------------------------------------------------------------------------
#define CVT_S0 51200      // w21a  640*320/4
#define CVT_S1 153600     // + w21b 640*640/4
#define CVT_S2 266240     // + w10a 640*704/4
#define CVT_S3 389120     // + w10b 768*640/4
#define CVT_S4 651264     // + l1f  4*2048*128/4
#define CVT_S5 749568     // + l2f  4*512*192/4
#define CVT_S6 1273856    // + radar 4*8192*64/4
#define CVT_BLOCKS ((CVT_S6 + 255) / 256)

__global__ __launch_bounds__(256)
void cvt_all(const float* __restrict__ w21a, const float* __restrict__ w21b,
             const float* __restrict__ w10a, const float* __restrict__ w10b,
             const float* __restrict__ l1f,  const float* __restrict__ l2f,
             const float* __restrict__ radar,
             __half* __restrict__ w21ah, __half* __restrict__ w21bh,
             __half* __restrict__ w10ah, __half* __restrict__ w10bh,
             __half* __restrict__ l1h,   __half* __restrict__ l2h,
             __half* __restrict__ rdh)
{
    int i = blockIdx.x * 256 + threadIdx.x;
    if (i >= CVT_S6) return;
    const float* src; __half* dst; int off;
    if      (i < CVT_S0) { src = w21a;  dst = w21ah; off = i; }
    else if (i < CVT_S1) { src = w21b;  dst = w21bh; off = i - CVT_S0; }
    else if (i < CVT_S2) { src = w10a;  dst = w10ah; off = i - CVT_S1; }
    else if (i < CVT_S3) { src = w10b;  dst = w10bh; off = i - CVT_S2; }
    else if (i < CVT_S4) { src = l1f;   dst = l1h;   off = i - CVT_S3; }
    else if (i < CVT_S5) { src = l2f;   dst = l2h;   off = i - CVT_S4; }
    else                 { src = radar; dst = rdh;   off = i - CVT_S5; }
    float4 v = ((const float4*)src)[off];
    ((__half2*)dst)[off*2+0] = __halves2half2(__float2half_rn(v.x), __float2half_rn(v.y));
    ((__half2*)dst)[off*2+1] = __halves2half2(__float2half_rn(v.z), __float2half_rn(v.w));
}

// ---------------------------------------------------------------------------
// combine: v = ReLU(sc*(H[n] + sum_j w_j G[idx_j]) + bb), fp16 in / fp16 out.
// ---------------------------------------------------------------------------
__global__ __launch_bounds__(256)
void combine_bn_relu(const __half* __restrict__ H,    // [B][Np][640] fp16
                     const __half* __restrict__ G,    // [B][Ng][640] fp16
                     const int*   __restrict__ knn_i,
                     const float* __restrict__ knn_w,
                     const float* __restrict__ bias,
                     const float* __restrict__ gamma,
                     const float* __restrict__ beta,
                     __half* __restrict__ Yh, int Np, int Ng)
{
    __shared__ float s_sc[640], s_bb[640];
    const float BNS = 0.99999500003749968f;   // 1/sqrt(1+1e-5)
    for (int c = threadIdx.x; c < 640; c += 256) {
        float sc = __ldg(gamma + c) * BNS;
        s_sc[c] = sc;
        s_bb[c] = sc * __ldg(bias + c) + __ldg(beta + c);
    }
    __syncthreads();
    const int b    = blockIdx.y;
    const int warp = threadIdx.x >> 5, lane = threadIdx.x & 31;
    const int n    = blockIdx.x * 8 + warp;
    const size_t pbase = (size_t)b * Np + n;

    int idx[8]; float w8[8];
    const int*   ip = knn_i + pbase * 8;
    const float* wp = knn_w + pbase * 8;
    #pragma unroll
    for (int j = 0; j < 8; ++j) { idx[j] = __ldg(ip + j); w8[j] = __ldg(wp + j); }

    const __half2* h2 = (const __half2*)(H + pbase * 640);
    float2 acc[10];
    #pragma unroll
    for (int r = 0; r < 10; ++r) acc[r] = __half22float2(__ldg(h2 + lane + 32 * r));
    #pragma unroll
    for (int j = 0; j < 8; ++j) {
        const __half2* g2 = (const __half2*)(G + ((size_t)b * Ng + idx[j]) * 640);
        const float wj = w8[j];
        #pragma unroll
        for (int r = 0; r < 10; ++r) {
            float2 gv = __half22float2(__ldg(g2 + lane + 32 * r));
            acc[r].x += wj * gv.x;
            acc[r].y += wj * gv.y;
        }
    }
    __half2* y2 = (__half2*)(Yh + pbase * 640);
    #pragma unroll
    for (int r = 0; r < 10; ++r) {
        int c = (lane + 32 * r) * 2;
        float vx = fmaxf(s_sc[c]     * acc[r].x + s_bb[c],     0.f);
        float vy = fmaxf(s_sc[c + 1] * acc[r].y + s_bb[c + 1], 0.f);
        y2[lane + 32 * r] = __floats2half2_rn(vx, vy);
    }
}

// ---------------------------------------------------------------------------
// mma.sync fp16 GEMM (R9/R12 config):  D[o][n] = sum_k W[o][k] * X[n][k]
// Block 128x128, K-chunk 64, 512 threads = 4x4 warps, warp tile 32x32.
// 3-stage cp.async pipeline, one __syncthreads per chunk. Stride 144 B.
// mode: 0 = channel-major fp32 + BN+ReLU (final output)
//       1 = point-major fp16 + BN+ReLU
//       2 = point-major fp16 raw
// ---------------------------------------------------------------------------
#define PLANE_BYTES 18432              // 128 rows x 144 B
#define STAGE_BYTES (2 * PLANE_BYTES)  // W, X
#define GEMM_SMEM   (3 * STAGE_BYTES)  // 110592; epilogue (67584 B) reuses it

__global__ __launch_bounds__(512)
void gemm_mma(const __half* __restrict__ Wh, int ldW,
              const __half* __restrict__ Xh,
              float* __restrict__ Yf, __half* __restrict__ Yhp,
              const float* __restrict__ bias, const float* __restrict__ gamma,
              const float* __restrict__ beta,
              int K, int N, int O, int mode)
{
    extern __shared__ char dsm[];
    const uint32_t sbase = smem_u32_of(dsm);
    const int t = threadIdx.x, lane = t & 31, w = t >> 5;
    const int wm = w >> 2, wn = w & 3;
    const int b  = blockIdx.z;
    const int n0 = blockIdx.x * 128;
    const int o0 = blockIdx.y * 128;

    const __half* srcs[2];
    srcs[0] = Wh + (size_t)o0 * ldW;
    srcs[1] = Xh + ((size_t)b * N + n0) * K;
    int lds[2] = { ldW, K };

    float accm[2][4][4];
    #pragma unroll
    for (int i = 0; i < 2; ++i)
        #pragma unroll
        for (int j = 0; j < 4; ++j)
            #pragma unroll
            for (int e = 0; e < 4; ++e) accm[i][j][e] = 0.f;

    auto cp_stage = [&](int k0, int buf) {
        uint32_t sb = sbase + buf * STAGE_BYTES;
        #pragma unroll
        for (int pl = 0; pl < 2; ++pl) {
            #pragma unroll
            for (int u = 0; u < 2; ++u) {
                int idx = t * 2 + u;            // 0..1023
                int row = idx >> 3, c8 = idx & 7;
                cp16(sb + pl * PLANE_BYTES + row * 144 + c8 * 16,
                     srcs[pl] + (size_t)row * lds[pl] + k0 + c8 * 8);
            }
        }
        asm volatile("cp.async.commit_group;" ::: "memory");
    };

    const int g = lane >> 3;
    const int arow_off = (g & 1) * 8 + (lane & 7);
    const int acol_off = (g >> 1) * 8;
    const int brow_off = (g >> 1) * 8 + (lane & 7);
    const int bcol_off = (g & 1) * 8;

    const int nc = K >> 6;
    cp_stage(0, 0);
    if (nc > 1) cp_stage(64, 1);

    int buf = 0;
    for (int it = 0; it < nc; ++it) {
        if (it + 1 < nc) asm volatile("cp.async.wait_group 1;" ::: "memory");
        else             asm volatile("cp.async.wait_group 0;" ::: "memory");
        __syncthreads();
        if (it + 2 < nc) {
            int nb = buf + 2; if (nb >= 3) nb -= 3;
            cp_stage((it + 2) << 6, nb);
        }

        const uint32_t pA = sbase + buf * STAGE_BYTES;
        const uint32_t pB = pA + PLANE_BYTES;
        #pragma unroll
        for (int ks = 0; ks < 4; ++ks) {
            uint32_t ah[2][4];
            #pragma unroll
            for (int mt = 0; mt < 2; ++mt) {
                uint32_t ad = (uint32_t)(wm * 32 + mt * 16 + arow_off) * 144
                            + (uint32_t)(ks * 16 + acol_off) * 2;
                ldsm4(ah[mt], pA + ad);
            }
            #pragma unroll
            for (int np = 0; np < 2; ++np) {
                uint32_t bd = (uint32_t)(wn * 32 + np * 16 + brow_off) * 144
                            + (uint32_t)(ks * 16 + bcol_off) * 2;
                uint32_t bh[4];
                ldsm4(bh, pB + bd);
                #pragma unroll
                for (int mt = 0; mt < 2; ++mt)
                    #pragma unroll
                    for (int nj = 0; nj < 2; ++nj)
                        mma16816(accm[mt][np * 2 + nj], ah[mt], bh + nj * 2);
            }
        }
        ++buf; if (buf == 3) buf = 0;
    }
    __syncthreads();   // all MMA reads done before smem reuse

    // ---- epilogue through smem (stride 132 floats) ----
    float* smf = (float*)dsm;
    const int base_r = wm * 32 + (lane >> 2);
    const int base_c = wn * 32 + (lane & 3) * 2;
    #pragma unroll
    for (int mt = 0; mt < 2; ++mt)
        #pragma unroll
        for (int nt = 0; nt < 4; ++nt) {
            float v0 = accm[mt][nt][0];
            float v1 = accm[mt][nt][1];
            float v2 = accm[mt][nt][2];
            float v3 = accm[mt][nt][3];
            int r = base_r + mt * 16, c = base_c + (nt >> 1) * 16 + (nt & 1) * 8;
            if (mode == 0) {
                smf[r * 132 + c]           = v0;
                smf[r * 132 + c + 1]       = v1;
                smf[(r + 8) * 132 + c]     = v2;
                smf[(r + 8) * 132 + c + 1] = v3;
            } else {
                smf[c * 132 + r]           = v0;
                smf[(c + 1) * 132 + r]     = v1;
                smf[c * 132 + r + 8]       = v2;
                smf[(c + 1) * 132 + r + 8] = v3;
            }
        }
    __syncthreads();

    const float BNS = 0.99999500003749968f;
    if (mode == 0) {
        int o = t >> 2, nch = (t & 3) * 32;
        float sc = __ldg(gamma + o0 + o) * BNS;
        float bb = sc * __ldg(bias + o0 + o) + __ldg(beta + o0 + o);
        float* dst = Yf + ((size_t)b * O + o0 + o) * N + n0 + nch;
        #pragma unroll
        for (int j = 0; j < 32; j += 4) {
            float4 v;
            v.x = fmaxf(sc * smf[o * 132 + nch + j]     + bb, 0.f);
            v.y = fmaxf(sc * smf[o * 132 + nch + j + 1] + bb, 0.f);
            v.z = fmaxf(sc * smf[o * 132 + nch + j + 2] + bb, 0.f);
            v.w = fmaxf(sc * smf[o * 132 + nch + j + 3] + bb, 0.f);
            *(float4*)(dst + j) = v;
        }
    } else {
        int n = t >> 2, och = (t & 3) * 32;
        size_t off = ((size_t)b * N + n0 + n) * O + o0 + och;
        #pragma unroll
        for (int j0 = 0; j0 < 32; j0 += 8) {
            union { __half h[8]; uint4 u; } Hh;
            #pragma unroll
            for (int j = 0; j < 8; ++j) {
                float v = smf[n * 132 + och + j0 + j];
                if (mode == 1) {
                    int o = o0 + och + j0 + j;
                    float sc = __ldg(gamma + o) * BNS;
                    float bb = sc * __ldg(bias + o) + __ldg(beta + o);
                    v = fmaxf(sc * v + bb, 0.f);
                }
                Hh.h[j] = __float2half_rn(v);
            }
            *(uint4*)(Yhp + off + j0) = Hh.u;
        }
    }
}

// ---------------------------------------------------------------------------
extern "C" void kernel_launch(void* const* d_in, const int* in_sizes, int n_in,
                              void* d_out, int out_size)
{
    const float* radar = (const float*)d_in[0];
    const float* l1f   = (const float*)d_in[1];
    const float* l2f   = (const float*)d_in[2];
    const float* l0_l1 = (const float*)d_in[3];
    const float* l1_l2 = (const float*)d_in[4];
    const float* w21a  = (const float*)d_in[5];
    const float* b21a  = (const float*)d_in[6];
    const float* g21a  = (const float*)d_in[7];
    const float* be21a = (const float*)d_in[8];
    const float* w21b  = (const float*)d_in[9];
    const float* b21b  = (const float*)d_in[10];
    const float* g21b  = (const float*)d_in[11];
    const float* be21b = (const float*)d_in[12];
    const float* w10a  = (const float*)d_in[13];
    const float* b10a  = (const float*)d_in[14];
    const float* g10a  = (const float*)d_in[15];
    const float* be10a = (const float*)d_in[16];
    const float* w10b  = (const float*)d_in[17];
    const float* b10b  = (const float*)d_in[18];
    const float* g10b  = (const float*)d_in[19];
    const float* be10b = (const float*)d_in[20];

    cudaFuncSetAttribute(gemm_mma, cudaFuncAttributeMaxDynamicSharedMemorySize, GEMM_SMEM);

    __half *l1h,*l2h,*rdh;
    __half *w21ah,*w21bh,*w10ah,*w10bh;
    __half *Y1h,*Fh,*Y3h,*G2,*H1,*G,*Hr;
    float *w1,*w0;
    int *i1,*i0;
    cudaGetSymbolAddress((void**)&l1h, g_l1h);
    cudaGetSymbolAddress((void**)&l2h, g_l2h);
    cudaGetSymbolAddress((void**)&rdh, g_rdh);
    cudaGetSymbolAddress((void**)&w21ah, g_w21ah);
    cudaGetSymbolAddress((void**)&w21bh, g_w21bh);
    cudaGetSymbolAddress((void**)&w10ah, g_w10ah);
    cudaGetSymbolAddress((void**)&w10bh, g_w10bh);
    cudaGetSymbolAddress((void**)&Y1h, g_Y1h);
    cudaGetSymbolAddress((void**)&Fh,  g_Fh);
    cudaGetSymbolAddress((void**)&Y3h, g_Y3h);
    cudaGetSymbolAddress((void**)&G2, g_G2);     cudaGetSymbolAddress((void**)&H1, g_H1);
    cudaGetSymbolAddress((void**)&G,  g_G);      cudaGetSymbolAddress((void**)&Hr, g_Hr);
    cudaGetSymbolAddress((void**)&i1, g_i1);     cudaGetSymbolAddress((void**)&w1, g_w1);
    cudaGetSymbolAddress((void**)&i0, g_i0);     cudaGetSymbolAddress((void**)&w0, g_w0);

    // ---- side stream for the KNN chain (parallel graph branch) ----
    // Created fresh per call and intentionally not destroyed (kernel_launch
    // runs only a few times; destroying mid-capture would invalidate capture).
    cudaStream_t sk;
    cudaStreamCreateWithFlags(&sk, cudaStreamNonBlocking);
    cudaEvent_t evFork, evK1, evK0;
    cudaEventCreateWithFlags(&evFork, cudaEventDisableTiming);
    cudaEventCreateWithFlags(&evK1,   cudaEventDisableTiming);
    cudaEventCreateWithFlags(&evK0,   cudaEventDisableTiming);

    cudaEventRecord(evFork, 0);
    cudaStreamWaitEvent(sk, evFork, 0);
    knn_topk<<<dim3(N1_/32, B_), 256, 0, sk>>>(l1_l2, N2_, N1_, i1, w1);
    cudaEventRecord(evK1, sk);
    knn_topk<<<dim3(N0_/32, B_), 256, 0, sk>>>(l0_l1, N1_, N0_, i0, w0);
    cudaEventRecord(evK0, sk);

    // ---- main stream: converts + GEMM chain ----
    cvt_all<<<CVT_BLOCKS, 256>>>(w21a, w21b, w10a, w10b, l1f, l2f, radar,
                                 w21ah, w21bh, w10ah, w10bh, l1h, l2h, rdh);

    gemm_mma<<<dim3(N1_/128, 5, B_), 512, GEMM_SMEM>>>(w21ah, 320, l1h,
        nullptr, H1, nullptr, nullptr, nullptr, 128, N1_, 640, 2);
    gemm_mma<<<dim3(N2_/128, 5, B_), 512, GEMM_SMEM>>>(w21ah+128, 320, l2h,
        nullptr, G2, nullptr, nullptr, nullptr, 192, N2_, 640, 2);

    cudaStreamWaitEvent(0, evK1, 0);
    combine_bn_relu<<<dim3(N1_/8, B_), 256>>>(H1, G2, i1, w1, b21a, g21a, be21a, Y1h, N1_, N2_);

    gemm_mma<<<dim3(N1_/128, 5, B_), 512, GEMM_SMEM>>>(w21bh, 640, Y1h,
        nullptr, Fh, b21b, g21b, be21b, 640, N1_, 640, 1);
    gemm_mma<<<dim3(N1_/128, 5, B_), 512, GEMM_SMEM>>>(w10ah+64, 704, Fh,
        nullptr, G, nullptr, nullptr, nullptr, 640, N1_, 640, 2);
    gemm_mma<<<dim3(N0_/128, 5, B_), 512, GEMM_SMEM>>>(w10ah, 704, rdh,
        nullptr, Hr, nullptr, nullptr, nullptr, 64, N0_, 640, 2);

    cudaStreamWaitEvent(0, evK0, 0);
    combine_bn_relu<<<dim3(N0_/8, B_), 256>>>(Hr, G, i0, w0, b10a, g10a, be10a, Y3h, N0_, N1_);

    gemm_mma<<<dim3(N0_/128, 6, B_), 512, GEMM_SMEM>>>(w10bh, 640, Y3h,
        (float*)d_out, nullptr, b10b, g10b, be10b, 640, N0_, 768, 0);
}

// round 15
// speedup vs baseline: 1.7520x; 1.0914x over previous
#include <cuda_runtime.h>
#include <cuda_fp16.h>
#include <cstdint>
#include <cstddef>

// ---------------------------------------------------------------------------
// FeaturePropogate via mma.sync fp16 (plain sm_103 PTX):
//   - interp pushed through first MLP layer (W*concat == W_a*feat + interp(W_b*F))
//   - GEMMs: fp16 mma.sync, fp32 accum; NEW: 256-thread CTAs, K-chunk 32,
//     3-stage cp.async, 2 CTAs/SM (smem 66KB, regs capped) for latency hiding
//   - KNN side-stream fork/join, fused converts, fp16 intermediates [R13]
// ---------------------------------------------------------------------------

#define B_     4
#define N0_    8192
#define N1_    2048
#define N2_    512

// ---- device scratch (no allocation allowed) ----
__device__ __half g_l1h[(size_t)B_*N1_*128];
__device__ __half g_l2h[(size_t)B_*N2_*192];
__device__ __half g_rdh[(size_t)B_*N0_*64];
__device__ __half g_w21ah[640*320];
__device__ __half g_w21bh[640*640];
__device__ __half g_w10ah[640*704];
__device__ __half g_w10bh[768*640];
__device__ __half g_Y1h[(size_t)B_*N1_*640];
__device__ __half g_Fh [(size_t)B_*N1_*640];
__device__ __half g_Y3h[(size_t)B_*N0_*640];
__device__ __half g_G2[(size_t)B_*N2_*640];
__device__ __half g_H1[(size_t)B_*N1_*640];
__device__ __half g_G [(size_t)B_*N1_*640];
__device__ __half g_Hr[(size_t)B_*N0_*640];
__device__ int   g_i1[(size_t)B_*N1_*8];
__device__ float g_w1[(size_t)B_*N1_*8];
__device__ int   g_i0[(size_t)B_*N0_*8];
__device__ float g_w0[(size_t)B_*N0_*8];

__device__ __forceinline__ uint32_t smem_u32_of(const void* p) {
    uint32_t a;
    asm("{ .reg .u64 t; cvta.to.shared.u64 t, %1; cvt.u32.u64 %0, t; }" : "=r"(a) : "l"(p));
    return a;
}
__device__ __forceinline__ void ldsm4(uint32_t* r, uint32_t addr) {
    asm volatile("ldmatrix.sync.aligned.m8n8.x4.shared.b16 {%0,%1,%2,%3}, [%4];"
                 : "=r"(r[0]), "=r"(r[1]), "=r"(r[2]), "=r"(r[3]) : "r"(addr));
}
__device__ __forceinline__ void mma16816(float* d, const uint32_t* a, const uint32_t* b) {
    asm volatile(
        "mma.sync.aligned.m16n8k16.row.col.f32.f16.f16.f32 "
        "{%0,%1,%2,%3}, {%4,%5,%6,%7}, {%8,%9}, {%0,%1,%2,%3};"
        : "+f"(d[0]), "+f"(d[1]), "+f"(d[2]), "+f"(d[3])
        : "r"(a[0]), "r"(a[1]), "r"(a[2]), "r"(a[3]), "r"(b[0]), "r"(b[1]));
}
__device__ __forceinline__ void cp16(uint32_t saddr, const void* gaddr) {
    asm volatile("cp.async.cg.shared.global [%0], [%1], 16;" :: "r"(saddr), "l"(gaddr));
}

// ---------------------------------------------------------------------------
// KNN top-8 (R11/R12 config): 256 threads = 32 points x 8 segments.
// ---------------------------------------------------------------------------
__global__ __launch_bounds__(256)
void knn_topk(const float* __restrict__ D, int M, int Npts,
              int* __restrict__ out_i, float* __restrict__ out_w)
{
    __shared__ float sd[32][8][8];
    __shared__ int   si[32][8][8];
    const int b   = blockIdx.y;
    const int p   = threadIdx.x & 31;
    const int q   = threadIdx.x >> 5;
    const int n   = blockIdx.x * 32 + p;
    const int seg = M >> 3;

    float bd[8]; int bi[8];
    #pragma unroll
    for (int j = 0; j < 8; ++j) { bd[j] = 3.4e38f; bi[j] = 0; }

    auto ins = [&](float v, int id) {
        if (v < bd[7]) {
            bd[7] = v; bi[7] = id;
            #pragma unroll
            for (int r = 7; r >= 1; --r) {
                if (bd[r] < bd[r-1]) {
                    float td = bd[r]; bd[r] = bd[r-1]; bd[r-1] = td;
                    int   ti = bi[r]; bi[r] = bi[r-1]; bi[r-1] = ti;
                }
            }
        }
    };

    const float* col = D + (size_t)b * M * Npts + n + (size_t)(q * seg) * Npts;
    const int mbase = q * seg;
    #pragma unroll 2
    for (int m = 0; m < seg; m += 4) {
        float v0 = __ldg(col + (size_t)(m + 0) * Npts);
        float v1 = __ldg(col + (size_t)(m + 1) * Npts);
        float v2 = __ldg(col + (size_t)(m + 2) * Npts);
        float v3 = __ldg(col + (size_t)(m + 3) * Npts);
        ins(v0, mbase + m);
        ins(v1, mbase + m + 1);
        ins(v2, mbase + m + 2);
        ins(v3, mbase + m + 3);
    }
    #pragma unroll
    for (int j = 0; j < 8; ++j) { sd[p][q][j] = bd[j]; si[p][q][j] = bi[j]; }
    __syncthreads();

    if (threadIdx.x < 32) {
        const int pp = threadIdx.x;
        int ptr[8];
        #pragma unroll
        for (int j = 0; j < 8; ++j) ptr[j] = 0;
        float d8[8]; int i8[8];
        #pragma unroll
        for (int k = 0; k < 8; ++k) {
            float best = sd[pp][0][ptr[0]]; int bq = 0;
            #pragma unroll
            for (int j = 1; j < 8; ++j) {
                float vj = sd[pp][j][ptr[j]];
                if (vj < best) { best = vj; bq = j; }
            }
            d8[k] = best;
            i8[k] = si[pp][bq][ptr[bq]++];
        }
        float w[8], s = 0.f;
        #pragma unroll
        for (int j = 0; j < 8; ++j) { w[j] = 1.f / (d8[j] + 1e-8f); s += w[j]; }
        float inv = 1.f / (s + 1e-8f);
        const int nn = blockIdx.x * 32 + pp;
        size_t base = ((size_t)b * Npts + nn) * 8;
        #pragma unroll
        for (int j = 0; j < 8; ++j) { out_i[base + j] = i8[j]; out_w[base + j] = w[j] * inv; }
    }
}

// ---------------------------------------------------------------------------
// fused converts: all 7 fp32 -> fp16 tensors in one launch.
// ---------------------------------------------------------------------------
#define CVT_S0 51200      // w21a  640*320/4
#define CVT_S1 153600     // + w21b 640*640/4
#define CVT_S2 266240     // + w10a 640*704/4
#define CVT_S3 389120     // + w10b 768*640/4
#define CVT_S4 651264     // + l1f  4*2048*128/4
#define CVT_S5 749568     // + l2f  4*512*192/4
#define CVT_S6 1273856    // + radar 4*8192*64/4
#define CVT_BLOCKS ((CVT_S6 + 255) / 256)

__global__ __launch_bounds__(256)
void cvt_all(const float* __restrict__ w21a, const float* __restrict__ w21b,
             const float* __restrict__ w10a, const float* __restrict__ w10b,
             const float* __restrict__ l1f,  const float* __restrict__ l2f,
             const float* __restrict__ radar,
             __half* __restrict__ w21ah, __half* __restrict__ w21bh,
             __half* __restrict__ w10ah, __half* __restrict__ w10bh,
             __half* __restrict__ l1h,   __half* __restrict__ l2h,
             __half* __restrict__ rdh)
{
    int i = blockIdx.x * 256 + threadIdx.x;
    if (i >= CVT_S6) return;
    const float* src; __half* dst; int off;
    if      (i < CVT_S0) { src = w21a;  dst = w21ah; off = i; }
    else if (i < CVT_S1) { src = w21b;  dst = w21bh; off = i - CVT_S0; }
    else if (i < CVT_S2) { src = w10a;  dst = w10ah; off = i - CVT_S1; }
    else if (i < CVT_S3) { src = w10b;  dst = w10bh; off = i - CVT_S2; }
    else if (i < CVT_S4) { src = l1f;   dst = l1h;   off = i - CVT_S3; }
    else if (i < CVT_S5) { src = l2f;   dst = l2h;   off = i - CVT_S4; }
    else                 { src = radar; dst = rdh;   off = i - CVT_S5; }
    float4 v = ((const float4*)src)[off];
    ((__half2*)dst)[off*2+0] = __halves2half2(__float2half_rn(v.x), __float2half_rn(v.y));
    ((__half2*)dst)[off*2+1] = __halves2half2(__float2half_rn(v.z), __float2half_rn(v.w));
}

// ---------------------------------------------------------------------------
// combine: v = ReLU(sc*(H[n] + sum_j w_j G[idx_j]) + bb), fp16 in / fp16 out.
// ---------------------------------------------------------------------------
__global__ __launch_bounds__(256)
void combine_bn_relu(const __half* __restrict__ H,    // [B][Np][640] fp16
                     const __half* __restrict__ G,    // [B][Ng][640] fp16
                     const int*   __restrict__ knn_i,
                     const float* __restrict__ knn_w,
                     const float* __restrict__ bias,
                     const float* __restrict__ gamma,
                     const float* __restrict__ beta,
                     __half* __restrict__ Yh, int Np, int Ng)
{
    __shared__ float s_sc[640], s_bb[640];
    const float BNS = 0.99999500003749968f;   // 1/sqrt(1+1e-5)
    for (int c = threadIdx.x; c < 640; c += 256) {
        float sc = __ldg(gamma + c) * BNS;
        s_sc[c] = sc;
        s_bb[c] = sc * __ldg(bias + c) + __ldg(beta + c);
    }
    __syncthreads();
    const int b    = blockIdx.y;
    const int warp = threadIdx.x >> 5, lane = threadIdx.x & 31;
    const int n    = blockIdx.x * 8 + warp;
    const size_t pbase = (size_t)b * Np + n;

    int idx[8]; float w8[8];
    const int*   ip = knn_i + pbase * 8;
    const float* wp = knn_w + pbase * 8;
    #pragma unroll
    for (int j = 0; j < 8; ++j) { idx[j] = __ldg(ip + j); w8[j] = __ldg(wp + j); }

    const __half2* h2 = (const __half2*)(H + pbase * 640);
    float2 acc[10];
    #pragma unroll
    for (int r = 0; r < 10; ++r) acc[r] = __half22float2(__ldg(h2 + lane + 32 * r));
    #pragma unroll
    for (int j = 0; j < 8; ++j) {
        const __half2* g2 = (const __half2*)(G + ((size_t)b * Ng + idx[j]) * 640);
        const float wj = w8[j];
        #pragma unroll
        for (int r = 0; r < 10; ++r) {
            float2 gv = __half22float2(__ldg(g2 + lane + 32 * r));
            acc[r].x += wj * gv.x;
            acc[r].y += wj * gv.y;
        }
    }
    __half2* y2 = (__half2*)(Yh + pbase * 640);
    #pragma unroll
    for (int r = 0; r < 10; ++r) {
        int c = (lane + 32 * r) * 2;
        float vx = fmaxf(s_sc[c]     * acc[r].x + s_bb[c],     0.f);
        float vy = fmaxf(s_sc[c + 1] * acc[r].y + s_bb[c + 1], 0.f);
        y2[lane + 32 * r] = __floats2half2_rn(vx, vy);
    }
}

// ---------------------------------------------------------------------------
// mma.sync fp16 GEMM:  D[o][n] = sum_k W[o][k] * X[n][k]
// Block 128x128, 256 threads = 4(m)x2(n) warps, warp tile 32x64.
// K-chunk 32, 3-stage cp.async pipeline, one __syncthreads per chunk.
// Smem row stride 80 B (conflict-free for LDSM). 2 CTAs/SM (66KB smem each).
// mode: 0 = channel-major fp32 + BN+ReLU (final output)
//       1 = point-major fp16 + BN+ReLU
//       2 = point-major fp16 raw
// ---------------------------------------------------------------------------
#define PLANE_BYTES 10240              // 128 rows x 80 B
#define STAGE_BYTES (2 * PLANE_BYTES)  // W, X
#define GEMM_SMEM   67584              // max(3*STAGE_BYTES=61440, epilogue 128*132*4)

__global__ __launch_bounds__(256, 2)
void gemm_mma(const __half* __restrict__ Wh, int ldW,
              const __half* __restrict__ Xh,
              float* __restrict__ Yf, __half* __restrict__ Yhp,
              const float* __restrict__ bias, const float* __restrict__ gamma,
              const float* __restrict__ beta,
              int K, int N, int O, int mode)
{
    extern __shared__ char dsm[];
    const uint32_t sbase = smem_u32_of(dsm);
    const int t = threadIdx.x, lane = t & 31, w = t >> 5;
    const int wm = w >> 1, wn = w & 1;     // warp tile: o = wm*32, n = wn*64
    const int b  = blockIdx.z;
    const int n0 = blockIdx.x * 128;
    const int o0 = blockIdx.y * 128;

    const __half* srcs[2];
    srcs[0] = Wh + (size_t)o0 * ldW;
    srcs[1] = Xh + ((size_t)b * N + n0) * K;
    int lds[2] = { ldW, K };

    float acc[2][8][4];
    #pragma unroll
    for (int i = 0; i < 2; ++i)
        #pragma unroll
        for (int j = 0; j < 8; ++j)
            #pragma unroll
            for (int e = 0; e < 4; ++e) acc[i][j][e] = 0.f;

    // stage loader: 2 planes x 128 rows x 32 halves (4 x 16B per row).
    // 512 cp16 per plane / 256 threads = two per thread per plane.
    auto cp_stage = [&](int k0, int buf) {
        uint32_t sb = sbase + buf * STAGE_BYTES;
        #pragma unroll
        for (int pl = 0; pl < 2; ++pl) {
            #pragma unroll
            for (int u = 0; u < 2; ++u) {
                int idx = t * 2 + u;            // 0..511
                int row = idx >> 2, c4 = idx & 3;
                cp16(sb + pl * PLANE_BYTES + row * 80 + c4 * 16,
                     srcs[pl] + (size_t)row * lds[pl] + k0 + c4 * 8);
            }
        }
        asm volatile("cp.async.commit_group;" ::: "memory");
    };

    const int g = lane >> 3;
    const int arow_off = (g & 1) * 8 + (lane & 7);
    const int acol_off = (g >> 1) * 8;
    const int brow_off = (g >> 1) * 8 + (lane & 7);
    const int bcol_off = (g & 1) * 8;

    const int nc = K >> 5;
    cp_stage(0, 0);
    if (nc > 1) cp_stage(32, 1);

    int buf = 0;
    for (int it = 0; it < nc; ++it) {
        if (it + 1 < nc) asm volatile("cp.async.wait_group 1;" ::: "memory");
        else             asm volatile("cp.async.wait_group 0;" ::: "memory");
        __syncthreads();
        if (it + 2 < nc) {
            int nb = buf + 2; if (nb >= 3) nb -= 3;
            cp_stage((it + 2) << 5, nb);
        }

        const uint32_t pA = sbase + buf * STAGE_BYTES;
        const uint32_t pB = pA + PLANE_BYTES;
        #pragma unroll
        for (int ks = 0; ks < 2; ++ks) {
            uint32_t ah[2][4];
            #pragma unroll
            for (int mt = 0; mt < 2; ++mt) {
                uint32_t ad = (uint32_t)(wm * 32 + mt * 16 + arow_off) * 80
                            + (uint32_t)(ks * 16 + acol_off) * 2;
                ldsm4(ah[mt], pA + ad);
            }
            #pragma unroll
            for (int np = 0; np < 4; ++np) {
                uint32_t bd = (uint32_t)(wn * 64 + np * 16 + brow_off) * 80
                            + (uint32_t)(ks * 16 + bcol_off) * 2;
                uint32_t bh[4];
                ldsm4(bh, pB + bd);
                #pragma unroll
                for (int mt = 0; mt < 2; ++mt)
                    #pragma unroll
                    for (int nj = 0; nj < 2; ++nj)
                        mma16816(acc[mt][np * 2 + nj], ah[mt], bh + nj * 2);
            }
        }
        ++buf; if (buf == 3) buf = 0;
    }
    __syncthreads();   // all MMA reads done before smem reuse

    // ---- epilogue through smem (stride 132 floats) ----
    float* smf = (float*)dsm;
    const int base_r = wm * 32 + (lane >> 2);
    const int base_c = wn * 64 + (lane & 3) * 2;
    #pragma unroll
    for (int mt = 0; mt < 2; ++mt)
        #pragma unroll
        for (int np = 0; np < 4; ++np)
            #pragma unroll
            for (int nj = 0; nj < 2; ++nj) {
                const float* a4 = acc[mt][np * 2 + nj];
                int r = base_r + mt * 16;
                int c = base_c + np * 16 + nj * 8;
                if (mode == 0) {
                    smf[r * 132 + c]           = a4[0];
                    smf[r * 132 + c + 1]       = a4[1];
                    smf[(r + 8) * 132 + c]     = a4[2];
                    smf[(r + 8) * 132 + c + 1] = a4[3];
                } else {
                    smf[c * 132 + r]           = a4[0];
                    smf[(c + 1) * 132 + r]     = a4[1];
                    smf[c * 132 + r + 8]       = a4[2];
                    smf[(c + 1) * 132 + r + 8] = a4[3];
                }
            }
    __syncthreads();

    const float BNS = 0.99999500003749968f;
    if (mode == 0) {
        int o = t >> 1, nch = (t & 1) * 64;
        float sc = __ldg(gamma + o0 + o) * BNS;
        float bb = sc * __ldg(bias + o0 + o) + __ldg(beta + o0 + o);
        float* dst = Yf + ((size_t)b * O + o0 + o) * N + n0 + nch;
        #pragma unroll
        for (int j = 0; j < 64; j += 4) {
            float4 v;
            v.x = fmaxf(sc * smf[o * 132 + nch + j]     + bb, 0.f);
            v.y = fmaxf(sc * smf[o * 132 + nch + j + 1] + bb, 0.f);
            v.z = fmaxf(sc * smf[o * 132 + nch + j + 2] + bb, 0.f);
            v.w = fmaxf(sc * smf[o * 132 + nch + j + 3] + bb, 0.f);
            *(float4*)(dst + j) = v;
        }
    } else {
        int n = t >> 1, och = (t & 1) * 64;
        size_t off = ((size_t)b * N + n0 + n) * O + o0 + och;
        #pragma unroll
        for (int j0 = 0; j0 < 64; j0 += 8) {
            union { __half h[8]; uint4 u; } Hh;
            #pragma unroll
            for (int j = 0; j < 8; ++j) {
                float v = smf[n * 132 + och + j0 + j];
                if (mode == 1) {
                    int o = o0 + och + j0 + j;
                    float sc = __ldg(gamma + o) * BNS;
                    float bb = sc * __ldg(bias + o) + __ldg(beta + o);
                    v = fmaxf(sc * v + bb, 0.f);
                }
                Hh.h[j] = __float2half_rn(v);
            }
            *(uint4*)(Yhp + off + j0) = Hh.u;
        }
    }
}

// ---------------------------------------------------------------------------
extern "C" void kernel_launch(void* const* d_in, const int* in_sizes, int n_in,
                              void* d_out, int out_size)
{
    const float* radar = (const float*)d_in[0];
    const float* l1f   = (const float*)d_in[1];
    const float* l2f   = (const float*)d_in[2];
    const float* l0_l1 = (const float*)d_in[3];
    const float* l1_l2 = (const float*)d_in[4];
    const float* w21a  = (const float*)d_in[5];
    const float* b21a  = (const float*)d_in[6];
    const float* g21a  = (const float*)d_in[7];
    const float* be21a = (const float*)d_in[8];
    const float* w21b  = (const float*)d_in[9];
    const float* b21b  = (const float*)d_in[10];
    const float* g21b  = (const float*)d_in[11];
    const float* be21b = (const float*)d_in[12];
    const float* w10a  = (const float*)d_in[13];
    const float* b10a  = (const float*)d_in[14];
    const float* g10a  = (const float*)d_in[15];
    const float* be10a = (const float*)d_in[16];
    const float* w10b  = (const float*)d_in[17];
    const float* b10b  = (const float*)d_in[18];
    const float* g10b  = (const float*)d_in[19];
    const float* be10b = (const float*)d_in[20];

    cudaFuncSetAttribute(gemm_mma, cudaFuncAttributeMaxDynamicSharedMemorySize, GEMM_SMEM);

    __half *l1h,*l2h,*rdh;
    __half *w21ah,*w21bh,*w10ah,*w10bh;
    __half *Y1h,*Fh,*Y3h,*G2,*H1,*G,*Hr;
    float *w1,*w0;
    int *i1,*i0;
    cudaGetSymbolAddress((void**)&l1h, g_l1h);
    cudaGetSymbolAddress((void**)&l2h, g_l2h);
    cudaGetSymbolAddress((void**)&rdh, g_rdh);
    cudaGetSymbolAddress((void**)&w21ah, g_w21ah);
    cudaGetSymbolAddress((void**)&w21bh, g_w21bh);
    cudaGetSymbolAddress((void**)&w10ah, g_w10ah);
    cudaGetSymbolAddress((void**)&w10bh, g_w10bh);
    cudaGetSymbolAddress((void**)&Y1h, g_Y1h);
    cudaGetSymbolAddress((void**)&Fh,  g_Fh);
    cudaGetSymbolAddress((void**)&Y3h, g_Y3h);
    cudaGetSymbolAddress((void**)&G2, g_G2);     cudaGetSymbolAddress((void**)&H1, g_H1);
    cudaGetSymbolAddress((void**)&G,  g_G);      cudaGetSymbolAddress((void**)&Hr, g_Hr);
    cudaGetSymbolAddress((void**)&i1, g_i1);     cudaGetSymbolAddress((void**)&w1, g_w1);
    cudaGetSymbolAddress((void**)&i0, g_i0);     cudaGetSymbolAddress((void**)&w0, g_w0);

    // ---- side stream for the KNN chain (parallel graph branch) ----
    cudaStream_t sk;
    cudaStreamCreateWithFlags(&sk, cudaStreamNonBlocking);
    cudaEvent_t evFork, evK1, evK0;
    cudaEventCreateWithFlags(&evFork, cudaEventDisableTiming);
    cudaEventCreateWithFlags(&evK1,   cudaEventDisableTiming);
    cudaEventCreateWithFlags(&evK0,   cudaEventDisableTiming);

    cudaEventRecord(evFork, 0);
    cudaStreamWaitEvent(sk, evFork, 0);
    knn_topk<<<dim3(N1_/32, B_), 256, 0, sk>>>(l1_l2, N2_, N1_, i1, w1);
    cudaEventRecord(evK1, sk);
    knn_topk<<<dim3(N0_/32, B_), 256, 0, sk>>>(l0_l1, N1_, N0_, i0, w0);
    cudaEventRecord(evK0, sk);

    // ---- main stream: converts + GEMM chain ----
    cvt_all<<<CVT_BLOCKS, 256>>>(w21a, w21b, w10a, w10b, l1f, l2f, radar,
                                 w21ah, w21bh, w10ah, w10bh, l1h, l2h, rdh);

    gemm_mma<<<dim3(N1_/128, 5, B_), 256, GEMM_SMEM>>>(w21ah, 320, l1h,
        nullptr, H1, nullptr, nullptr, nullptr, 128, N1_, 640, 2);
    gemm_mma<<<dim3(N2_/128, 5, B_), 256, GEMM_SMEM>>>(w21ah+128, 320, l2h,
        nullptr, G2, nullptr, nullptr, nullptr, 192, N2_, 640, 2);

    cudaStreamWaitEvent(0, evK1, 0);
    combine_bn_relu<<<dim3(N1_/8, B_), 256>>>(H1, G2, i1, w1, b21a, g21a, be21a, Y1h, N1_, N2_);

    gemm_mma<<<dim3(N1_/128, 5, B_), 256, GEMM_SMEM>>>(w21bh, 640, Y1h,
        nullptr, Fh, b21b, g21b, be21b, 640, N1_, 640, 1);
    gemm_mma<<<dim3(N1_/128, 5, B_), 256, GEMM_SMEM>>>(w10ah+64, 704, Fh,
        nullptr, G, nullptr, nullptr, nullptr, 640, N1_, 640, 2);
    gemm_mma<<<dim3(N0_/128, 5, B_), 256, GEMM_SMEM>>>(w10ah, 704, rdh,
        nullptr, Hr, nullptr, nullptr, nullptr, 64, N0_, 640, 2);

    cudaStreamWaitEvent(0, evK0, 0);
    combine_bn_relu<<<dim3(N0_/8, B_), 256>>>(Hr, G, i0, w0, b10a, g10a, be10a, Y3h, N0_, N1_);

    gemm_mma<<<dim3(N0_/128, 6, B_), 256, GEMM_SMEM>>>(w10bh, 640, Y3h,
        (float*)d_out, nullptr, b10b, g10b, be10b, 640, N0_, 768, 0);
}